// round 10
// baseline (speedup 1.0000x reference)
#include <cuda_runtime.h>
#include <math.h>
#include <stdint.h>

// Problem constants
#define BSZ 2
#define TLEN 2048
#define CDIM 1024
#define HN 16
#define DH 64
#define MROWS (BSZ * TLEN)   // 4096

// Scratch (allocation-free rule: __device__ globals)
__device__ float g_qkv[(size_t)MROWS * 3 * CDIM];   // tf32 values
__device__ float g_y[(size_t)MROWS * CDIM];         // tf32 values
__device__ float g_xc[(size_t)MROWS * CDIM];        // tf32(x)
__device__ float g_wt[(size_t)4 * CDIM * CDIM];     // tf32(W_attn^T), tf32(W_proj^T)
__device__ float g_vt[(size_t)BSZ * HN * DH * TLEN]; // V transposed: [b,h,d,t]

// ---------------------------------------------------------------------------
// helpers
// ---------------------------------------------------------------------------
__device__ __forceinline__ float to_tf32(float x) {
    uint32_t u;
    asm("cvt.rna.tf32.f32 %0, %1;" : "=r"(u) : "f"(x));
    return __uint_as_float(u);
}

__device__ __forceinline__ void mma_tf32(float* d, const uint32_t* a, const uint32_t* b) {
    asm volatile(
        "mma.sync.aligned.m16n8k8.row.col.f32.tf32.tf32.f32 "
        "{%0,%1,%2,%3}, {%4,%5,%6,%7}, {%8,%9}, {%0,%1,%2,%3};"
        : "+f"(d[0]), "+f"(d[1]), "+f"(d[2]), "+f"(d[3])
        : "r"(a[0]), "r"(a[1]), "r"(a[2]), "r"(a[3]), "r"(b[0]), "r"(b[1]));
}

__device__ __forceinline__ uint32_t smem_u32(const void* p) {
    uint32_t a;
    asm("{ .reg .u64 t; cvta.to.shared.u64 t, %1; cvt.u32.u64 %0, t; }"
        : "=r"(a) : "l"(p));
    return a;
}

__device__ __forceinline__ void ldsm_x4(uint32_t* r, uint32_t addr) {
    asm volatile("ldmatrix.sync.aligned.m8n8.x4.shared.b16 {%0,%1,%2,%3}, [%4];"
                 : "=r"(r[0]), "=r"(r[1]), "=r"(r[2]), "=r"(r[3]) : "r"(addr));
}

// a-frag (16x8, [m][k] smem): mats: (mlo,klo),(mhi,klo),(mlo,khi),(mhi,khi)
__device__ __forceinline__ uint32_t a_frag_off(int lane, int stride) {
    int mat = lane >> 3, rw = lane & 7;
    return (uint32_t)(((8 * (mat & 1) + rw) * stride + 4 * (mat >> 1)) * 4);
}
// b-frag pair (2 n-tiles, [n][k] smem): mats: (nt0,klo),(nt0,khi),(nt1,klo),(nt1,khi)
__device__ __forceinline__ uint32_t b_frag_off(int lane, int stride) {
    int mat = lane >> 3, rw = lane & 7;
    return (uint32_t)(((8 * (mat >> 1) + rw) * stride + 4 * (mat & 1)) * 4);
}

#define CP16(s, g) \
    asm volatile("cp.async.cg.shared.global [%0], [%1], 16;" :: "r"(s), "l"(g) : "memory")
#define CP_COMMIT() asm volatile("cp.async.commit_group;" ::: "memory")
#define CP_WAIT(n)  asm volatile("cp.async.wait_group %0;" :: "n"(n) : "memory")

// ---------------------------------------------------------------------------
// x -> tf32 conversion
// ---------------------------------------------------------------------------
__global__ __launch_bounds__(256) void cvt_kernel(const float* __restrict__ x)
{
    size_t i = ((size_t)blockIdx.x * 256 + threadIdx.x) * 4;
    float4 v = *(const float4*)(x + i);
    *(float4*)(g_xc + i) = make_float4(to_tf32(v.x), to_tf32(v.y),
                                       to_tf32(v.z), to_tf32(v.w));
}

// ---------------------------------------------------------------------------
// Weight transpose + tf32: src[K][N] -> g_wt(+off)[N][K]
// ---------------------------------------------------------------------------
__global__ __launch_bounds__(256) void transpose_kernel(
    const float* __restrict__ src, int K, int N, int sel)
{
    __shared__ float t[32][33];
    float* dst = g_wt + (sel ? (size_t)3 * CDIM * CDIM : 0);
    const int nb = blockIdx.x * 32, kb = blockIdx.y * 32;
    const int x = threadIdx.x, y = threadIdx.y;
#pragma unroll
    for (int j = 0; j < 32; j += 8)
        t[y + j][x] = src[(size_t)(kb + y + j) * N + nb + x];
    __syncthreads();
#pragma unroll
    for (int j = 0; j < 32; j += 8)
        dst[(size_t)(nb + y + j) * K + kb + x] = to_tf32(t[x][y + j]);
}

// ---------------------------------------------------------------------------
// V transpose: g_qkv V slice [b,t,(h,d)] -> g_vt[b,h,d,t]
// ---------------------------------------------------------------------------
__global__ __launch_bounds__(256) void vtrans_kernel()
{
    __shared__ float t[32][33];
    const int b = blockIdx.z;
    const int h = blockIdx.y >> 1;
    const int d0 = (blockIdx.y & 1) * 32;
    const int t0 = blockIdx.x * 32;
    const int x = threadIdx.x, y = threadIdx.y;

    const float* src = g_qkv + (size_t)b * TLEN * 3 * CDIM + 2 * CDIM + h * DH;
#pragma unroll
    for (int j = 0; j < 32; j += 8)
        t[y + j][x] = src[(size_t)(t0 + y + j) * 3 * CDIM + d0 + x];
    __syncthreads();
    float* dst = g_vt + ((size_t)(b * HN + h) * DH + d0) * TLEN + t0;
#pragma unroll
    for (int j = 0; j < 32; j += 8)
        dst[(size_t)(y + j) * TLEN + x] = t[x][y + j];
}

// ---------------------------------------------------------------------------
// tf32 GEMM (unchanged from R9): 128x128 tile, 128 threads = 4 warps (2m x 2n),
// 2-stage cp.async ring -> 3 CTAs/SM.
// ---------------------------------------------------------------------------
#define SA 36
#define TBYTES (128 * SA * 4)
#define STAGEB (2 * TBYTES)
#define GSTAGES 2
#define GSMEM (GSTAGES * STAGEB)     // 73728

__global__ __launch_bounds__(128, 3) void gemm_ls_kernel(
    const float* __restrict__ bias, float* __restrict__ C_param,
    int M, int N, int K, int mode)
{
    extern __shared__ float smg[];
    const float* A  = mode ? g_y : g_xc;
    const float* Bt = g_wt + (mode ? (size_t)3 * CDIM * CDIM : 0);
    float*       C  = mode ? C_param : g_qkv;

    const int tid = threadIdx.x, lane = tid & 31, wid = tid >> 5;
    const int wm = wid >> 1, wn = wid & 1;
    const int g = lane >> 2, q = lane & 3;
    const int m0 = blockIdx.y * 128, n0 = blockIdx.x * 128;
    const uint32_t sb = smem_u32(smg);

    const uint32_t a_off = a_frag_off(lane, SA);
    const uint32_t b_off = b_frag_off(lane, SA);

    float acc[4][8][4];
#pragma unroll
    for (int mt = 0; mt < 4; mt++)
#pragma unroll
        for (int nt = 0; nt < 8; nt++)
#pragma unroll
            for (int e = 0; e < 4; e++) acc[mt][nt][e] = 0.f;

    const int nc = K / 32;

#pragma unroll
    for (int s = 0; s < 2; s++) {
        const int k0 = s * 32;
        const uint32_t st = sb + (uint32_t)(s * STAGEB);
#pragma unroll
        for (int i = 0; i < 8; i++) {
            const int f = tid + 128 * i;
            const int row = f >> 3, c4 = f & 7;
            const uint32_t so = st + (uint32_t)((row * SA + c4 * 4) * 4);
            CP16(so, A + (size_t)(m0 + row) * K + k0 + c4 * 4);
            CP16(so + TBYTES, Bt + (size_t)(n0 + row) * K + k0 + c4 * 4);
        }
        CP_COMMIT();
    }

    for (int c = 0; c < nc; c++) {
        if (c == nc - 1) { CP_WAIT(0); } else { CP_WAIT(1); }
        __syncthreads();

        const uint32_t ab = sb + (uint32_t)((c & 1) * STAGEB);
        const uint32_t bbse = ab + TBYTES;
#pragma unroll
        for (int kk = 0; kk < 32; kk += 8) {
            uint32_t af[4][4], bf[4][4];
#pragma unroll
            for (int mt = 0; mt < 4; mt++)
                ldsm_x4(af[mt], ab + (uint32_t)(((wm * 64 + mt * 16) * SA + kk) * 4) + a_off);
#pragma unroll
            for (int pr = 0; pr < 4; pr++)
                ldsm_x4(bf[pr], bbse + (uint32_t)(((wn * 64 + pr * 16) * SA + kk) * 4) + b_off);
#pragma unroll
            for (int mt = 0; mt < 4; mt++)
#pragma unroll
                for (int nt = 0; nt < 8; nt++)
                    mma_tf32(acc[mt][nt], af[mt], bf[nt >> 1] + (nt & 1) * 2);
        }
        __syncthreads();

        if (c + 2 < nc) {
            const int k0 = (c + 2) * 32;
            const uint32_t st = sb + (uint32_t)((c & 1) * STAGEB);
#pragma unroll
            for (int i = 0; i < 8; i++) {
                const int f = tid + 128 * i;
                const int row = f >> 3, c4 = f & 7;
                const uint32_t so = st + (uint32_t)((row * SA + c4 * 4) * 4);
                CP16(so, A + (size_t)(m0 + row) * K + k0 + c4 * 4);
                CP16(so + TBYTES, Bt + (size_t)(n0 + row) * K + k0 + c4 * 4);
            }
            CP_COMMIT();
        }
    }

#pragma unroll
    for (int mt = 0; mt < 4; mt++) {
        int r0 = m0 + wm * 64 + mt * 16 + g;
#pragma unroll
        for (int nt = 0; nt < 8; nt++) {
            int cc = n0 + wn * 64 + nt * 8 + 2 * q;
            float b0 = bias[cc], b1 = bias[cc + 1];
            float v00 = acc[mt][nt][0] + b0, v01 = acc[mt][nt][1] + b1;
            float v10 = acc[mt][nt][2] + b0, v11 = acc[mt][nt][3] + b1;
            if (mode == 0) {
                v00 = to_tf32(v00); v01 = to_tf32(v01);
                v10 = to_tf32(v10); v11 = to_tf32(v11);
            }
            *(float2*)(C + (size_t)r0 * N + cc)       = make_float2(v00, v01);
            *(float2*)(C + (size_t)(r0 + 8) * N + cc) = make_float2(v10, v11);
        }
    }
}

// ---------------------------------------------------------------------------
// Flash attention, 128-QUERY tile, 256 threads = 8 warps (16 rows each).
// Pre-transposed V. Smem: K [64xSKA] | Vt [64xSKA] | P/Qstage [128xSKA]
// = 69,632 B -> 2 CTAs/SM (16 warps). Half the K/V load+sync phases of the
// 64-query version.
// ---------------------------------------------------------------------------
#define SKA 68
#define TILE_F (64 * SKA)
#define TILE_B (TILE_F * 4)          // 17408
#define ASMEM (4 * TILE_B)           // K + Vt + P(128 rows) = 69632

__global__ __launch_bounds__(256, 2) void attn_vt_kernel()
{
    extern __shared__ float sm[];

    const int qt = (gridDim.x - 1) - blockIdx.x;   // heavy-first
    const int h = blockIdx.y, b = blockIdx.z;
    const int tid = threadIdx.x, lane = tid & 31, w = tid >> 5;
    const int g = lane >> 2, q = lane & 3;
    const int q0 = qt * 128;

    const uint32_t sb = smem_u32(sm);
    const uint32_t sK = sb, sVt = sb + TILE_B, sP = sb + 2 * TILE_B;
    float* Ps = sm + 2 * TILE_F;

    const size_t rs = 3 * CDIM;
    const float* qb  = g_qkv + (size_t)b * TLEN * rs + h * DH;
    const float* kb  = qb + CDIM;
    const float* vtb = g_vt + (size_t)(b * HN + h) * DH * TLEN;

    const int lrow = tid >> 4;             // 0..15
    const int lcol = (tid & 15) * 4;       // 0..60
    const uint32_t aoff = a_frag_off(lane, SKA);
    const uint32_t boff = b_frag_off(lane, SKA);

    // ---- load Q (128 rows) into P buffer, hoist fragments (scaled 0.125) ----
#pragma unroll
    for (int p = 0; p < 8; p++) {
        CP16(sP + (uint32_t)(((lrow + 16 * p) * SKA + lcol) * 4),
             qb + (size_t)(q0 + lrow + 16 * p) * rs + lcol);
    }
    CP_COMMIT(); CP_WAIT(0);
    __syncthreads();

    uint32_t qf[8][4];
#pragma unroll
    for (int kd = 0; kd < 8; kd++) {
        ldsm_x4(qf[kd], sP + (uint32_t)(((w * 16) * SKA + kd * 8) * 4) + aoff);
#pragma unroll
        for (int e = 0; e < 4; e++)
            qf[kd][e] = __float_as_uint(__uint_as_float(qf[kd][e]) * 0.125f);
    }

    float so[8][4];
    float mrow[2] = {-1e30f, -1e30f}, lsum[2] = {0.f, 0.f};
#pragma unroll
    for (int nt = 0; nt < 8; nt++)
#pragma unroll
        for (int e = 0; e < 4; e++) so[nt][e] = 0.f;

    const int nkt = 2 * qt + 2;            // 64-key tiles covering keys <= q0+127
    for (int kt = 0; kt < nkt; kt++) {
        __syncthreads();   // prev iter's K/Vt/P reads complete (also Q hoist on kt=0)
        {
            const int k0r = kt * 64;
#pragma unroll
            for (int p = 0; p < 4; p++) {
                CP16(sK + (uint32_t)(((lrow + 16 * p) * SKA + lcol) * 4),
                     kb + (size_t)(k0r + lrow + 16 * p) * rs + lcol);
                CP16(sVt + (uint32_t)(((lrow + 16 * p) * SKA + lcol) * 4),
                     vtb + (size_t)(lrow + 16 * p) * TLEN + k0r + lcol);
            }
            CP_COMMIT(); CP_WAIT(0);
        }
        __syncthreads();

        // ---- S = Q K^T ----
        float sc[8][4];
#pragma unroll
        for (int nt = 0; nt < 8; nt++)
#pragma unroll
            for (int e = 0; e < 4; e++) sc[nt][e] = 0.f;

#pragma unroll
        for (int kd = 0; kd < 8; kd++) {
            uint32_t bf[4][4];
#pragma unroll
            for (int pr = 0; pr < 4; pr++)
                ldsm_x4(bf[pr], sK + (uint32_t)(((pr * 16) * SKA + kd * 8) * 4) + boff);
#pragma unroll
            for (int nt = 0; nt < 8; nt++)
                mma_tf32(sc[nt], qf[kd], bf[nt >> 1] + (nt & 1) * 2);
        }

        // ---- causal mask (global indices) when tile crosses this warp's rows ----
        {
            const int r0g = q0 + w * 16 + g;        // thread's first global row
            const int cbase = kt * 64;
            if (cbase + 63 > r0g) {                 // tile not fully below diagonal
                const int r1g = r0g + 8;
#pragma unroll
                for (int nt = 0; nt < 8; nt++) {
                    const int c = cbase + nt * 8 + 2 * q;
                    if (c     > r0g) sc[nt][0] = -1e30f;
                    if (c + 1 > r0g) sc[nt][1] = -1e30f;
                    if (c     > r1g) sc[nt][2] = -1e30f;
                    if (c + 1 > r1g) sc[nt][3] = -1e30f;
                }
            }
        }

        // ---- online softmax (2 rows per thread) ----
        float mx0 = -1e30f, mx1 = -1e30f;
#pragma unroll
        for (int nt = 0; nt < 8; nt++) {
            mx0 = fmaxf(mx0, fmaxf(sc[nt][0], sc[nt][1]));
            mx1 = fmaxf(mx1, fmaxf(sc[nt][2], sc[nt][3]));
        }
        mx0 = fmaxf(mx0, __shfl_xor_sync(0xffffffffu, mx0, 1));
        mx0 = fmaxf(mx0, __shfl_xor_sync(0xffffffffu, mx0, 2));
        mx1 = fmaxf(mx1, __shfl_xor_sync(0xffffffffu, mx1, 1));
        mx1 = fmaxf(mx1, __shfl_xor_sync(0xffffffffu, mx1, 2));

        const float mn0 = fmaxf(mrow[0], mx0);
        const float mn1 = fmaxf(mrow[1], mx1);
        const float al0 = __expf(mrow[0] - mn0);
        const float al1 = __expf(mrow[1] - mn1);
        mrow[0] = mn0; mrow[1] = mn1;

        float s0 = 0.f, s1 = 0.f;
#pragma unroll
        for (int nt = 0; nt < 8; nt++) {
            sc[nt][0] = __expf(sc[nt][0] - mn0); s0 += sc[nt][0];
            sc[nt][1] = __expf(sc[nt][1] - mn0); s0 += sc[nt][1];
            sc[nt][2] = __expf(sc[nt][2] - mn1); s1 += sc[nt][2];
            sc[nt][3] = __expf(sc[nt][3] - mn1); s1 += sc[nt][3];
        }
        s0 += __shfl_xor_sync(0xffffffffu, s0, 1);
        s0 += __shfl_xor_sync(0xffffffffu, s0, 2);
        s1 += __shfl_xor_sync(0xffffffffu, s1, 1);
        s1 += __shfl_xor_sync(0xffffffffu, s1, 2);
        lsum[0] = lsum[0] * al0 + s0;
        lsum[1] = lsum[1] * al1 + s1;

#pragma unroll
        for (int nt = 0; nt < 8; nt++) {
            so[nt][0] *= al0; so[nt][1] *= al0;
            so[nt][2] *= al1; so[nt][3] *= al1;
        }

        // ---- store P (tf32) into own warp rows of the 128-row P buffer ----
        {
            const int r0 = w * 16 + g;
#pragma unroll
            for (int nt = 0; nt < 8; nt++) {
                const int c = nt * 8 + 2 * q;
                *(float2*)&Ps[r0 * SKA + c] =
                    make_float2(to_tf32(sc[nt][0]), to_tf32(sc[nt][1]));
                *(float2*)&Ps[(r0 + 8) * SKA + c] =
                    make_float2(to_tf32(sc[nt][2]), to_tf32(sc[nt][3]));
            }
        }
        __syncwarp();   // P rows owned/read by this warp only

        // ---- O += P V  (b-frags from pre-transposed V: [d][key]) ----
#pragma unroll
        for (int kd = 0; kd < 8; kd++) {
            uint32_t pf[4], bf[4][4];
            ldsm_x4(pf, sP + (uint32_t)(((w * 16) * SKA + kd * 8) * 4) + aoff);
#pragma unroll
            for (int pr = 0; pr < 4; pr++)
                ldsm_x4(bf[pr], sVt + (uint32_t)(((pr * 16) * SKA + kd * 8) * 4) + boff);
#pragma unroll
            for (int nt = 0; nt < 8; nt++)
                mma_tf32(so[nt], pf, bf[nt >> 1] + (nt & 1) * 2);
        }
    }

    // ---- normalize + store y (tf32 for GEMM2 consumption) ----
    {
        const float inv0 = 1.f / lsum[0];
        const float inv1 = 1.f / lsum[1];
        const int r0 = q0 + w * 16 + g;
        float* yb = g_y + (size_t)b * TLEN * CDIM + h * DH;
#pragma unroll
        for (int nt = 0; nt < 8; nt++) {
            const int c = nt * 8 + 2 * q;
            *(float2*)(yb + (size_t)r0 * CDIM + c) =
                make_float2(to_tf32(so[nt][0] * inv0), to_tf32(so[nt][1] * inv0));
            *(float2*)(yb + (size_t)(r0 + 8) * CDIM + c) =
                make_float2(to_tf32(so[nt][2] * inv1), to_tf32(so[nt][3] * inv1));
        }
    }
}

// ---------------------------------------------------------------------------
extern "C" void kernel_launch(void* const* d_in, const int* in_sizes, int n_in,
                              void* d_out, int out_size)
{
    const float* x      = (const float*)d_in[0];
    const float* W_attn = (const float*)d_in[1];
    const float* b_attn = (const float*)d_in[2];
    const float* W_proj = (const float*)d_in[3];
    const float* b_proj = (const float*)d_in[4];
    float* out = (float*)d_out;

    cudaFuncSetAttribute(gemm_ls_kernel, cudaFuncAttributeMaxDynamicSharedMemorySize, GSMEM);
    cudaFuncSetAttribute(attn_vt_kernel, cudaFuncAttributeMaxDynamicSharedMemorySize, ASMEM);

    // 0) pre-convert x; transpose+convert weights
    cvt_kernel<<<(MROWS * CDIM) / (256 * 4), 256>>>(x);
    {
        dim3 tb(32, 8);
        transpose_kernel<<<dim3((3 * CDIM) / 32, CDIM / 32), tb>>>(W_attn, CDIM, 3 * CDIM, 0);
        transpose_kernel<<<dim3(CDIM / 32, CDIM / 32), tb>>>(W_proj, CDIM, CDIM, 1);
    }
    // 1) qkv = x @ W_attn + b_attn (tf32-rounded)
    {
        dim3 grid((3 * CDIM) / 128, MROWS / 128);
        gemm_ls_kernel<<<grid, 128, GSMEM>>>(b_attn, nullptr, MROWS, 3 * CDIM, CDIM, 0);
    }
    // 1b) transpose V slice: g_qkv -> g_vt[b,h,d,t]
    {
        dim3 tb(32, 8);
        vtrans_kernel<<<dim3(TLEN / 32, 2 * HN, BSZ), tb>>>();
    }
    // 2) flash attention (128-query tiles) -> g_y (tf32-rounded)
    {
        dim3 grid(TLEN / 128, HN, BSZ);
        attn_vt_kernel<<<grid, 256, ASMEM>>>();
    }
    // 3) out = y @ W_proj + b_proj
    {
        dim3 grid(CDIM / 128, MROWS / 128);
        gemm_ls_kernel<<<grid, 128, GSMEM>>>(b_proj, out, MROWS, CDIM, CDIM, 1);
    }
}

// round 11
// speedup vs baseline: 1.0494x; 1.0494x over previous
#include <cuda_runtime.h>
#include <math.h>
#include <stdint.h>

// Problem constants
#define BSZ 2
#define TLEN 2048
#define CDIM 1024
#define HN 16
#define DH 64
#define MROWS (BSZ * TLEN)   // 4096

// Scratch (allocation-free rule: __device__ globals)
__device__ float g_qkv[(size_t)MROWS * 3 * CDIM];   // tf32 values
__device__ float g_y[(size_t)MROWS * CDIM];         // tf32 values
__device__ float g_xc[(size_t)MROWS * CDIM];        // tf32(x)
__device__ float g_wt[(size_t)4 * CDIM * CDIM];     // tf32(W_attn^T), tf32(W_proj^T)
__device__ float g_vt[(size_t)BSZ * HN * DH * TLEN]; // V transposed: [b,h,d,t]

// ---------------------------------------------------------------------------
// helpers
// ---------------------------------------------------------------------------
__device__ __forceinline__ float to_tf32(float x) {
    uint32_t u;
    asm("cvt.rna.tf32.f32 %0, %1;" : "=r"(u) : "f"(x));
    return __uint_as_float(u);
}

__device__ __forceinline__ void mma_tf32(float* d, const uint32_t* a, const uint32_t* b) {
    asm volatile(
        "mma.sync.aligned.m16n8k8.row.col.f32.tf32.tf32.f32 "
        "{%0,%1,%2,%3}, {%4,%5,%6,%7}, {%8,%9}, {%0,%1,%2,%3};"
        : "+f"(d[0]), "+f"(d[1]), "+f"(d[2]), "+f"(d[3])
        : "r"(a[0]), "r"(a[1]), "r"(a[2]), "r"(a[3]), "r"(b[0]), "r"(b[1]));
}

__device__ __forceinline__ uint32_t smem_u32(const void* p) {
    uint32_t a;
    asm("{ .reg .u64 t; cvta.to.shared.u64 t, %1; cvt.u32.u64 %0, t; }"
        : "=r"(a) : "l"(p));
    return a;
}

__device__ __forceinline__ void ldsm_x4(uint32_t* r, uint32_t addr) {
    asm volatile("ldmatrix.sync.aligned.m8n8.x4.shared.b16 {%0,%1,%2,%3}, [%4];"
                 : "=r"(r[0]), "=r"(r[1]), "=r"(r[2]), "=r"(r[3]) : "r"(addr));
}

// a-frag (16x8, [m][k] smem): mats: (mlo,klo),(mhi,klo),(mlo,khi),(mhi,khi)
__device__ __forceinline__ uint32_t a_frag_off(int lane, int stride) {
    int mat = lane >> 3, rw = lane & 7;
    return (uint32_t)(((8 * (mat & 1) + rw) * stride + 4 * (mat >> 1)) * 4);
}
// b-frag pair (2 n-tiles, [n][k] smem): mats: (nt0,klo),(nt0,khi),(nt1,klo),(nt1,khi)
__device__ __forceinline__ uint32_t b_frag_off(int lane, int stride) {
    int mat = lane >> 3, rw = lane & 7;
    return (uint32_t)(((8 * (mat >> 1) + rw) * stride + 4 * (mat & 1)) * 4);
}

#define CP16(s, g) \
    asm volatile("cp.async.cg.shared.global [%0], [%1], 16;" :: "r"(s), "l"(g) : "memory")
#define CP_COMMIT() asm volatile("cp.async.commit_group;" ::: "memory")
#define CP_WAIT(n)  asm volatile("cp.async.wait_group %0;" :: "n"(n) : "memory")

// ---------------------------------------------------------------------------
// x -> tf32 conversion
// ---------------------------------------------------------------------------
__global__ __launch_bounds__(256) void cvt_kernel(const float* __restrict__ x)
{
    size_t i = ((size_t)blockIdx.x * 256 + threadIdx.x) * 4;
    float4 v = *(const float4*)(x + i);
    *(float4*)(g_xc + i) = make_float4(to_tf32(v.x), to_tf32(v.y),
                                       to_tf32(v.z), to_tf32(v.w));
}

// ---------------------------------------------------------------------------
// Weight transpose + tf32: src[K][N] -> g_wt(+off)[N][K]
// ---------------------------------------------------------------------------
__global__ __launch_bounds__(256) void transpose_kernel(
    const float* __restrict__ src, int K, int N, int sel)
{
    __shared__ float t[32][33];
    float* dst = g_wt + (sel ? (size_t)3 * CDIM * CDIM : 0);
    const int nb = blockIdx.x * 32, kb = blockIdx.y * 32;
    const int x = threadIdx.x, y = threadIdx.y;
#pragma unroll
    for (int j = 0; j < 32; j += 8)
        t[y + j][x] = src[(size_t)(kb + y + j) * N + nb + x];
    __syncthreads();
#pragma unroll
    for (int j = 0; j < 32; j += 8)
        dst[(size_t)(nb + y + j) * K + kb + x] = to_tf32(t[x][y + j]);
}

// ---------------------------------------------------------------------------
// V transpose: g_qkv V slice [b,t,(h,d)] -> g_vt[b,h,d,t]
// ---------------------------------------------------------------------------
__global__ __launch_bounds__(256) void vtrans_kernel()
{
    __shared__ float t[32][33];
    const int b = blockIdx.z;
    const int h = blockIdx.y >> 1;
    const int d0 = (blockIdx.y & 1) * 32;
    const int t0 = blockIdx.x * 32;
    const int x = threadIdx.x, y = threadIdx.y;

    const float* src = g_qkv + (size_t)b * TLEN * 3 * CDIM + 2 * CDIM + h * DH;
#pragma unroll
    for (int j = 0; j < 32; j += 8)
        t[y + j][x] = src[(size_t)(t0 + y + j) * 3 * CDIM + d0 + x];
    __syncthreads();
    float* dst = g_vt + ((size_t)(b * HN + h) * DH + d0) * TLEN + t0;
#pragma unroll
    for (int j = 0; j < 32; j += 8)
        dst[(size_t)(y + j) * TLEN + x] = t[x][y + j];
}

// ---------------------------------------------------------------------------
// tf32 GEMM (unchanged from R9): 128x128 tile, 128 threads = 4 warps (2m x 2n),
// 2-stage cp.async ring -> 3 CTAs/SM.
// ---------------------------------------------------------------------------
#define SA 36
#define TBYTES (128 * SA * 4)
#define STAGEB (2 * TBYTES)
#define GSTAGES 2
#define GSMEM (GSTAGES * STAGEB)     // 73728

__global__ __launch_bounds__(128, 3) void gemm_ls_kernel(
    const float* __restrict__ bias, float* __restrict__ C_param,
    int M, int N, int K, int mode)
{
    extern __shared__ float smg[];
    const float* A  = mode ? g_y : g_xc;
    const float* Bt = g_wt + (mode ? (size_t)3 * CDIM * CDIM : 0);
    float*       C  = mode ? C_param : g_qkv;

    const int tid = threadIdx.x, lane = tid & 31, wid = tid >> 5;
    const int wm = wid >> 1, wn = wid & 1;
    const int g = lane >> 2, q = lane & 3;
    const int m0 = blockIdx.y * 128, n0 = blockIdx.x * 128;
    const uint32_t sb = smem_u32(smg);

    const uint32_t a_off = a_frag_off(lane, SA);
    const uint32_t b_off = b_frag_off(lane, SA);

    float acc[4][8][4];
#pragma unroll
    for (int mt = 0; mt < 4; mt++)
#pragma unroll
        for (int nt = 0; nt < 8; nt++)
#pragma unroll
            for (int e = 0; e < 4; e++) acc[mt][nt][e] = 0.f;

    const int nc = K / 32;

#pragma unroll
    for (int s = 0; s < 2; s++) {
        const int k0 = s * 32;
        const uint32_t st = sb + (uint32_t)(s * STAGEB);
#pragma unroll
        for (int i = 0; i < 8; i++) {
            const int f = tid + 128 * i;
            const int row = f >> 3, c4 = f & 7;
            const uint32_t so = st + (uint32_t)((row * SA + c4 * 4) * 4);
            CP16(so, A + (size_t)(m0 + row) * K + k0 + c4 * 4);
            CP16(so + TBYTES, Bt + (size_t)(n0 + row) * K + k0 + c4 * 4);
        }
        CP_COMMIT();
    }

    for (int c = 0; c < nc; c++) {
        if (c == nc - 1) { CP_WAIT(0); } else { CP_WAIT(1); }
        __syncthreads();

        const uint32_t ab = sb + (uint32_t)((c & 1) * STAGEB);
        const uint32_t bbse = ab + TBYTES;
#pragma unroll
        for (int kk = 0; kk < 32; kk += 8) {
            uint32_t af[4][4], bf[4][4];
#pragma unroll
            for (int mt = 0; mt < 4; mt++)
                ldsm_x4(af[mt], ab + (uint32_t)(((wm * 64 + mt * 16) * SA + kk) * 4) + a_off);
#pragma unroll
            for (int pr = 0; pr < 4; pr++)
                ldsm_x4(bf[pr], bbse + (uint32_t)(((wn * 64 + pr * 16) * SA + kk) * 4) + b_off);
#pragma unroll
            for (int mt = 0; mt < 4; mt++)
#pragma unroll
                for (int nt = 0; nt < 8; nt++)
                    mma_tf32(acc[mt][nt], af[mt], bf[nt >> 1] + (nt & 1) * 2);
        }
        __syncthreads();

        if (c + 2 < nc) {
            const int k0 = (c + 2) * 32;
            const uint32_t st = sb + (uint32_t)((c & 1) * STAGEB);
#pragma unroll
            for (int i = 0; i < 8; i++) {
                const int f = tid + 128 * i;
                const int row = f >> 3, c4 = f & 7;
                const uint32_t so = st + (uint32_t)((row * SA + c4 * 4) * 4);
                CP16(so, A + (size_t)(m0 + row) * K + k0 + c4 * 4);
                CP16(so + TBYTES, Bt + (size_t)(n0 + row) * K + k0 + c4 * 4);
            }
            CP_COMMIT();
        }
    }

#pragma unroll
    for (int mt = 0; mt < 4; mt++) {
        int r0 = m0 + wm * 64 + mt * 16 + g;
#pragma unroll
        for (int nt = 0; nt < 8; nt++) {
            int cc = n0 + wn * 64 + nt * 8 + 2 * q;
            float b0 = bias[cc], b1 = bias[cc + 1];
            float v00 = acc[mt][nt][0] + b0, v01 = acc[mt][nt][1] + b1;
            float v10 = acc[mt][nt][2] + b0, v11 = acc[mt][nt][3] + b1;
            if (mode == 0) {
                v00 = to_tf32(v00); v01 = to_tf32(v01);
                v10 = to_tf32(v10); v11 = to_tf32(v11);
            }
            *(float2*)(C + (size_t)r0 * N + cc)       = make_float2(v00, v01);
            *(float2*)(C + (size_t)(r0 + 8) * N + cc) = make_float2(v10, v11);
        }
    }
}

// ---------------------------------------------------------------------------
// Flash attention, 64-query tile, 128 threads = 4 warps, DOUBLE-BUFFERED K/V
// at 3 CTAs/SM. Buffers: K0|Vt0|K1|Vt1 (4 x 17,408 = 69,632 B). P has no own
// buffer: after S-mma retires K_cur (barrier), P overwrites K_cur (each warp
// touches only its own 16 rows). Q stages through K1 before the pipeline.
// ---------------------------------------------------------------------------
#define SKA 68
#define TILE_F (64 * SKA)
#define TILE_B (TILE_F * 4)          // 17408
#define ASMEM (4 * TILE_B)           // 69632

__global__ __launch_bounds__(128, 3) void attn_db3_kernel()
{
    extern __shared__ float sm[];

    const int qt = (gridDim.x - 1) - blockIdx.x;   // heavy-first
    const int h = blockIdx.y, b = blockIdx.z;
    const int tid = threadIdx.x, lane = tid & 31, w = tid >> 5;
    const int g = lane >> 2, q = lane & 3;
    const int q0 = qt * 64;

    const uint32_t sb = smem_u32(sm);

    const size_t rs = 3 * CDIM;
    const float* qb  = g_qkv + (size_t)b * TLEN * rs + h * DH;
    const float* kb  = qb + CDIM;
    const float* vtb = g_vt + (size_t)(b * HN + h) * DH * TLEN;

    const int lrow = tid >> 4;             // 0..7
    const int lcol = (tid & 15) * 4;       // 0..60
    const uint32_t aoff = a_frag_off(lane, SKA);
    const uint32_t boff = b_frag_off(lane, SKA);

    // ---- preload: Q into K1 region; K/Vt tile 0 into parity-0 buffers ----
    {
        const uint32_t sQ = sb + 2 * TILE_B;        // K1
#pragma unroll
        for (int p = 0; p < 8; p++) {
            const uint32_t ro = (uint32_t)(((lrow + 8 * p) * SKA + lcol) * 4);
            CP16(sQ + ro, qb + (size_t)(q0 + lrow + 8 * p) * rs + lcol);
            CP16(sb + ro, kb + (size_t)(lrow + 8 * p) * rs + lcol);
            CP16(sb + TILE_B + ro, vtb + (size_t)(lrow + 8 * p) * TLEN + lcol);
        }
        CP_COMMIT(); CP_WAIT(0);
    }
    __syncthreads();

    // hoist Q fragments (scaled by 1/sqrt(64), exact)
    uint32_t qf[8][4];
#pragma unroll
    for (int kd = 0; kd < 8; kd++) {
        ldsm_x4(qf[kd], sb + 2 * TILE_B + (uint32_t)(((w * 16) * SKA + kd * 8) * 4) + aoff);
#pragma unroll
        for (int e = 0; e < 4; e++)
            qf[kd][e] = __float_as_uint(__uint_as_float(qf[kd][e]) * 0.125f);
    }

    float so[8][4];
    float mrow[2] = {-1e30f, -1e30f}, lsum[2] = {0.f, 0.f};
#pragma unroll
    for (int nt = 0; nt < 8; nt++)
#pragma unroll
        for (int e = 0; e < 4; e++) so[nt][e] = 0.f;

    for (int kt = 0; kt <= qt; kt++) {
        const int p = kt & 1;
        const uint32_t sK  = sb + (uint32_t)(p * 2 * TILE_B);
        const uint32_t sVt = sK + TILE_B;
        float* Ps = sm + p * 2 * TILE_F;   // aliases K_cur (after barrier C)

        // barrier A: prev iter's PV reads of parity 1-p fully complete
        // (at kt==0 this also covers the Q-fragment hoist from K1)
        __syncthreads();

        // issue prefetch of tile kt+1 into parity 1-p
        if (kt < qt) {
            const uint32_t nK = sb + (uint32_t)((1 - p) * 2 * TILE_B);
            const int k0r = (kt + 1) * 64;
#pragma unroll
            for (int pp = 0; pp < 8; pp++) {
                const uint32_t ro = (uint32_t)(((lrow + 8 * pp) * SKA + lcol) * 4);
                CP16(nK + ro, kb + (size_t)(k0r + lrow + 8 * pp) * rs + lcol);
                CP16(nK + TILE_B + ro, vtb + (size_t)(lrow + 8 * pp) * TLEN + k0r + lcol);
            }
            CP_COMMIT();
            CP_WAIT(1);     // tile kt resident; tile kt+1 stays in flight
        } else {
            CP_WAIT(0);
        }
        __syncthreads();    // barrier B: K_p/Vt_p visible to all warps

        // ---- S = Q K^T ----
        float sc[8][4];
#pragma unroll
        for (int nt = 0; nt < 8; nt++)
#pragma unroll
            for (int e = 0; e < 4; e++) sc[nt][e] = 0.f;

#pragma unroll
        for (int kd = 0; kd < 8; kd++) {
            uint32_t bf[4][4];
#pragma unroll
            for (int pr = 0; pr < 4; pr++)
                ldsm_x4(bf[pr], sK + (uint32_t)(((pr * 16) * SKA + kd * 8) * 4) + boff);
#pragma unroll
            for (int nt = 0; nt < 8; nt++)
                mma_tf32(sc[nt], qf[kd], bf[nt >> 1] + (nt & 1) * 2);
        }

        // ---- causal mask on diagonal tile ----
        if (kt == qt) {
            const int r0 = w * 16 + g, r1 = r0 + 8;
#pragma unroll
            for (int nt = 0; nt < 8; nt++) {
                const int c = nt * 8 + 2 * q;
                if (c     > r0) sc[nt][0] = -1e30f;
                if (c + 1 > r0) sc[nt][1] = -1e30f;
                if (c     > r1) sc[nt][2] = -1e30f;
                if (c + 1 > r1) sc[nt][3] = -1e30f;
            }
        }

        // ---- online softmax (2 rows per thread) ----
        float mx0 = -1e30f, mx1 = -1e30f;
#pragma unroll
        for (int nt = 0; nt < 8; nt++) {
            mx0 = fmaxf(mx0, fmaxf(sc[nt][0], sc[nt][1]));
            mx1 = fmaxf(mx1, fmaxf(sc[nt][2], sc[nt][3]));
        }
        mx0 = fmaxf(mx0, __shfl_xor_sync(0xffffffffu, mx0, 1));
        mx0 = fmaxf(mx0, __shfl_xor_sync(0xffffffffu, mx0, 2));
        mx1 = fmaxf(mx1, __shfl_xor_sync(0xffffffffu, mx1, 1));
        mx1 = fmaxf(mx1, __shfl_xor_sync(0xffffffffu, mx1, 2));

        const float mn0 = fmaxf(mrow[0], mx0);
        const float mn1 = fmaxf(mrow[1], mx1);
        const float al0 = __expf(mrow[0] - mn0);
        const float al1 = __expf(mrow[1] - mn1);
        mrow[0] = mn0; mrow[1] = mn1;

        float s0 = 0.f, s1 = 0.f;
#pragma unroll
        for (int nt = 0; nt < 8; nt++) {
            sc[nt][0] = __expf(sc[nt][0] - mn0); s0 += sc[nt][0];
            sc[nt][1] = __expf(sc[nt][1] - mn0); s0 += sc[nt][1];
            sc[nt][2] = __expf(sc[nt][2] - mn1); s1 += sc[nt][2];
            sc[nt][3] = __expf(sc[nt][3] - mn1); s1 += sc[nt][3];
        }
        s0 += __shfl_xor_sync(0xffffffffu, s0, 1);
        s0 += __shfl_xor_sync(0xffffffffu, s0, 2);
        s1 += __shfl_xor_sync(0xffffffffu, s1, 1);
        s1 += __shfl_xor_sync(0xffffffffu, s1, 2);
        lsum[0] = lsum[0] * al0 + s0;
        lsum[1] = lsum[1] * al1 + s1;

#pragma unroll
        for (int nt = 0; nt < 8; nt++) {
            so[nt][0] *= al0; so[nt][1] *= al0;
            so[nt][2] *= al1; so[nt][3] *= al1;
        }

        __syncthreads();    // barrier C: every warp done reading K_p (S-mma)

        // ---- store P (tf32) over K_p rows (own warp rows only) ----
        {
            const int r0 = w * 16 + g;
#pragma unroll
            for (int nt = 0; nt < 8; nt++) {
                const int c = nt * 8 + 2 * q;
                *(float2*)&Ps[r0 * SKA + c] =
                    make_float2(to_tf32(sc[nt][0]), to_tf32(sc[nt][1]));
                *(float2*)&Ps[(r0 + 8) * SKA + c] =
                    make_float2(to_tf32(sc[nt][2]), to_tf32(sc[nt][3]));
            }
        }
        __syncwarp();   // P rows owned/read by this warp only

        // ---- O += P V  (b-frags from pre-transposed V: [d][key]) ----
#pragma unroll
        for (int kd = 0; kd < 8; kd++) {
            uint32_t pf[4], bf[4][4];
            ldsm_x4(pf, sK + (uint32_t)(((w * 16) * SKA + kd * 8) * 4) + aoff);
#pragma unroll
            for (int pr = 0; pr < 4; pr++)
                ldsm_x4(bf[pr], sVt + (uint32_t)(((pr * 16) * SKA + kd * 8) * 4) + boff);
#pragma unroll
            for (int nt = 0; nt < 8; nt++)
                mma_tf32(so[nt], pf, bf[nt >> 1] + (nt & 1) * 2);
        }
    }

    // ---- normalize + store y (tf32 for GEMM2 consumption) ----
    {
        const float inv0 = 1.f / lsum[0];
        const float inv1 = 1.f / lsum[1];
        const int r0 = q0 + w * 16 + g;
        float* yb = g_y + (size_t)b * TLEN * CDIM + h * DH;
#pragma unroll
        for (int nt = 0; nt < 8; nt++) {
            const int c = nt * 8 + 2 * q;
            *(float2*)(yb + (size_t)r0 * CDIM + c) =
                make_float2(to_tf32(so[nt][0] * inv0), to_tf32(so[nt][1] * inv0));
            *(float2*)(yb + (size_t)(r0 + 8) * CDIM + c) =
                make_float2(to_tf32(so[nt][2] * inv1), to_tf32(so[nt][3] * inv1));
        }
    }
}

// ---------------------------------------------------------------------------
extern "C" void kernel_launch(void* const* d_in, const int* in_sizes, int n_in,
                              void* d_out, int out_size)
{
    const float* x      = (const float*)d_in[0];
    const float* W_attn = (const float*)d_in[1];
    const float* b_attn = (const float*)d_in[2];
    const float* W_proj = (const float*)d_in[3];
    const float* b_proj = (const float*)d_in[4];
    float* out = (float*)d_out;

    cudaFuncSetAttribute(gemm_ls_kernel, cudaFuncAttributeMaxDynamicSharedMemorySize, GSMEM);
    cudaFuncSetAttribute(attn_db3_kernel, cudaFuncAttributeMaxDynamicSharedMemorySize, ASMEM);

    // 0) pre-convert x; transpose+convert weights
    cvt_kernel<<<(MROWS * CDIM) / (256 * 4), 256>>>(x);
    {
        dim3 tb(32, 8);
        transpose_kernel<<<dim3((3 * CDIM) / 32, CDIM / 32), tb>>>(W_attn, CDIM, 3 * CDIM, 0);
        transpose_kernel<<<dim3(CDIM / 32, CDIM / 32), tb>>>(W_proj, CDIM, CDIM, 1);
    }
    // 1) qkv = x @ W_attn + b_attn (tf32-rounded)
    {
        dim3 grid((3 * CDIM) / 128, MROWS / 128);
        gemm_ls_kernel<<<grid, 128, GSMEM>>>(b_attn, nullptr, MROWS, 3 * CDIM, CDIM, 0);
    }
    // 1b) transpose V slice: g_qkv -> g_vt[b,h,d,t]
    {
        dim3 tb(32, 8);
        vtrans_kernel<<<dim3(TLEN / 32, 2 * HN, BSZ), tb>>>();
    }
    // 2) flash attention (64-query tiles, double-buffered) -> g_y
    {
        dim3 grid(TLEN / 64, HN, BSZ);
        attn_db3_kernel<<<grid, 128, ASMEM>>>();
    }
    // 3) out = y @ W_proj + b_proj
    {
        dim3 grid(CDIM / 128, MROWS / 128);
        gemm_ls_kernel<<<grid, 128, GSMEM>>>(b_proj, out, MROWS, CDIM, CDIM, 1);
    }
}

// round 12
// speedup vs baseline: 1.1944x; 1.1382x over previous
#include <cuda_runtime.h>
#include <cuda_fp16.h>
#include <math.h>
#include <stdint.h>

// Problem constants
#define BSZ 2
#define TLEN 2048
#define CDIM 1024
#define HN 16
#define DH 64
#define MROWS (BSZ * TLEN)   // 4096

// Scratch (allocation-free rule: __device__ globals)
__device__ float g_qkv[(size_t)MROWS * 3 * CDIM];   // tf32 values
__device__ float g_y[(size_t)MROWS * CDIM];         // tf32 values
__device__ float g_xc[(size_t)MROWS * CDIM];        // tf32(x)
__device__ float g_wt[(size_t)4 * CDIM * CDIM];     // tf32(W_attn^T), tf32(W_proj^T)
__device__ __half g_vt[(size_t)BSZ * HN * DH * TLEN]; // V transposed fp16: [b,h,d,t]

// ---------------------------------------------------------------------------
// helpers
// ---------------------------------------------------------------------------
__device__ __forceinline__ float to_tf32(float x) {
    uint32_t u;
    asm("cvt.rna.tf32.f32 %0, %1;" : "=r"(u) : "f"(x));
    return __uint_as_float(u);
}

__device__ __forceinline__ void mma_tf32(float* d, const uint32_t* a, const uint32_t* b) {
    asm volatile(
        "mma.sync.aligned.m16n8k8.row.col.f32.tf32.tf32.f32 "
        "{%0,%1,%2,%3}, {%4,%5,%6,%7}, {%8,%9}, {%0,%1,%2,%3};"
        : "+f"(d[0]), "+f"(d[1]), "+f"(d[2]), "+f"(d[3])
        : "r"(a[0]), "r"(a[1]), "r"(a[2]), "r"(a[3]), "r"(b[0]), "r"(b[1]));
}

__device__ __forceinline__ void mma_f16(float* d, const uint32_t* a, const uint32_t* b) {
    asm volatile(
        "mma.sync.aligned.m16n8k16.row.col.f32.f16.f16.f32 "
        "{%0,%1,%2,%3}, {%4,%5,%6,%7}, {%8,%9}, {%0,%1,%2,%3};"
        : "+f"(d[0]), "+f"(d[1]), "+f"(d[2]), "+f"(d[3])
        : "r"(a[0]), "r"(a[1]), "r"(a[2]), "r"(a[3]), "r"(b[0]), "r"(b[1]));
}

// pack two fp32 -> fp16x2 reg, lo = first k element, hi = second
__device__ __forceinline__ uint32_t pack_f16(float lo, float hi) {
    uint32_t r;
    asm("cvt.rn.f16x2.f32 %0, %1, %2;" : "=r"(r) : "f"(hi), "f"(lo));
    return r;
}

__device__ __forceinline__ float ex2f(float x) {
    float r;
    asm("ex2.approx.f32 %0, %1;" : "=f"(r) : "f"(x));
    return r;
}

__device__ __forceinline__ uint32_t smem_u32(const void* p) {
    uint32_t a;
    asm("{ .reg .u64 t; cvta.to.shared.u64 t, %1; cvt.u32.u64 %0, t; }"
        : "=r"(a) : "l"(p));
    return a;
}

__device__ __forceinline__ void ldsm_x4(uint32_t* r, uint32_t addr) {
    asm volatile("ldmatrix.sync.aligned.m8n8.x4.shared.b16 {%0,%1,%2,%3}, [%4];"
                 : "=r"(r[0]), "=r"(r[1]), "=r"(r[2]), "=r"(r[3]) : "r"(addr));
}

// a-frag (16x8, [m][k] smem): mats: (mlo,klo),(mhi,klo),(mlo,khi),(mhi,khi)
__device__ __forceinline__ uint32_t a_frag_off(int lane, int stride) {
    int mat = lane >> 3, rw = lane & 7;
    return (uint32_t)(((8 * (mat & 1) + rw) * stride + 4 * (mat >> 1)) * 4);
}
// b-frag pair (2 n-tiles, [n][k] smem): mats: (nt0,klo),(nt0,khi),(nt1,klo),(nt1,khi)
__device__ __forceinline__ uint32_t b_frag_off(int lane, int stride) {
    int mat = lane >> 3, rw = lane & 7;
    return (uint32_t)(((8 * (mat >> 1) + rw) * stride + 4 * (mat & 1)) * 4);
}

#define CP16(s, g) \
    asm volatile("cp.async.cg.shared.global [%0], [%1], 16;" :: "r"(s), "l"(g) : "memory")
#define CP_COMMIT() asm volatile("cp.async.commit_group;" ::: "memory")
#define CP_WAIT(n)  asm volatile("cp.async.wait_group %0;" :: "n"(n) : "memory")

// ---------------------------------------------------------------------------
// x -> tf32 conversion
// ---------------------------------------------------------------------------
__global__ __launch_bounds__(256) void cvt_kernel(const float* __restrict__ x)
{
    size_t i = ((size_t)blockIdx.x * 256 + threadIdx.x) * 4;
    float4 v = *(const float4*)(x + i);
    *(float4*)(g_xc + i) = make_float4(to_tf32(v.x), to_tf32(v.y),
                                       to_tf32(v.z), to_tf32(v.w));
}

// ---------------------------------------------------------------------------
// Weight transpose + tf32: src[K][N] -> g_wt(+off)[N][K]
// ---------------------------------------------------------------------------
__global__ __launch_bounds__(256) void transpose_kernel(
    const float* __restrict__ src, int K, int N, int sel)
{
    __shared__ float t[32][33];
    float* dst = g_wt + (sel ? (size_t)3 * CDIM * CDIM : 0);
    const int nb = blockIdx.x * 32, kb = blockIdx.y * 32;
    const int x = threadIdx.x, y = threadIdx.y;
#pragma unroll
    for (int j = 0; j < 32; j += 8)
        t[y + j][x] = src[(size_t)(kb + y + j) * N + nb + x];
    __syncthreads();
#pragma unroll
    for (int j = 0; j < 32; j += 8)
        dst[(size_t)(nb + y + j) * K + kb + x] = to_tf32(t[x][y + j]);
}

// ---------------------------------------------------------------------------
// V transpose to fp16: g_qkv V slice [b,t,(h,d)] -> g_vt[b,h,d,t] (half)
// ---------------------------------------------------------------------------
__global__ __launch_bounds__(256) void vtrans_kernel()
{
    __shared__ float t[32][33];
    const int b = blockIdx.z;
    const int h = blockIdx.y >> 1;
    const int d0 = (blockIdx.y & 1) * 32;
    const int t0 = blockIdx.x * 32;
    const int x = threadIdx.x, y = threadIdx.y;

    const float* src = g_qkv + (size_t)b * TLEN * 3 * CDIM + 2 * CDIM + h * DH;
#pragma unroll
    for (int j = 0; j < 32; j += 8)
        t[y + j][x] = src[(size_t)(t0 + y + j) * 3 * CDIM + d0 + x];
    __syncthreads();
    __half* dst = g_vt + ((size_t)(b * HN + h) * DH + d0) * TLEN + t0;
#pragma unroll
    for (int j = 0; j < 32; j += 8)
        dst[(size_t)(y + j) * TLEN + x] = __float2half(t[x][y + j]);
}

// ---------------------------------------------------------------------------
// tf32 GEMM (unchanged from R9): 128x128 tile, 128 threads = 4 warps (2m x 2n),
// 2-stage cp.async ring -> 3 CTAs/SM.
// ---------------------------------------------------------------------------
#define SA 36
#define TBYTES (128 * SA * 4)
#define STAGEB (2 * TBYTES)
#define GSTAGES 2
#define GSMEM (GSTAGES * STAGEB)     // 73728

__global__ __launch_bounds__(128, 3) void gemm_ls_kernel(
    const float* __restrict__ bias, float* __restrict__ C_param,
    int M, int N, int K, int mode)
{
    extern __shared__ float smg[];
    const float* A  = mode ? g_y : g_xc;
    const float* Bt = g_wt + (mode ? (size_t)3 * CDIM * CDIM : 0);
    float*       C  = mode ? C_param : g_qkv;

    const int tid = threadIdx.x, lane = tid & 31, wid = tid >> 5;
    const int wm = wid >> 1, wn = wid & 1;
    const int g = lane >> 2, q = lane & 3;
    const int m0 = blockIdx.y * 128, n0 = blockIdx.x * 128;
    const uint32_t sb = smem_u32(smg);

    const uint32_t a_off = a_frag_off(lane, SA);
    const uint32_t b_off = b_frag_off(lane, SA);

    float acc[4][8][4];
#pragma unroll
    for (int mt = 0; mt < 4; mt++)
#pragma unroll
        for (int nt = 0; nt < 8; nt++)
#pragma unroll
            for (int e = 0; e < 4; e++) acc[mt][nt][e] = 0.f;

    const int nc = K / 32;

#pragma unroll
    for (int s = 0; s < 2; s++) {
        const int k0 = s * 32;
        const uint32_t st = sb + (uint32_t)(s * STAGEB);
#pragma unroll
        for (int i = 0; i < 8; i++) {
            const int f = tid + 128 * i;
            const int row = f >> 3, c4 = f & 7;
            const uint32_t so = st + (uint32_t)((row * SA + c4 * 4) * 4);
            CP16(so, A + (size_t)(m0 + row) * K + k0 + c4 * 4);
            CP16(so + TBYTES, Bt + (size_t)(n0 + row) * K + k0 + c4 * 4);
        }
        CP_COMMIT();
    }

    for (int c = 0; c < nc; c++) {
        if (c == nc - 1) { CP_WAIT(0); } else { CP_WAIT(1); }
        __syncthreads();

        const uint32_t ab = sb + (uint32_t)((c & 1) * STAGEB);
        const uint32_t bbse = ab + TBYTES;
#pragma unroll
        for (int kk = 0; kk < 32; kk += 8) {
            uint32_t af[4][4], bf[4][4];
#pragma unroll
            for (int mt = 0; mt < 4; mt++)
                ldsm_x4(af[mt], ab + (uint32_t)(((wm * 64 + mt * 16) * SA + kk) * 4) + a_off);
#pragma unroll
            for (int pr = 0; pr < 4; pr++)
                ldsm_x4(bf[pr], bbse + (uint32_t)(((wn * 64 + pr * 16) * SA + kk) * 4) + b_off);
#pragma unroll
            for (int mt = 0; mt < 4; mt++)
#pragma unroll
                for (int nt = 0; nt < 8; nt++)
                    mma_tf32(acc[mt][nt], af[mt], bf[nt >> 1] + (nt & 1) * 2);
        }
        __syncthreads();

        if (c + 2 < nc) {
            const int k0 = (c + 2) * 32;
            const uint32_t st = sb + (uint32_t)((c & 1) * STAGEB);
#pragma unroll
            for (int i = 0; i < 8; i++) {
                const int f = tid + 128 * i;
                const int row = f >> 3, c4 = f & 7;
                const uint32_t so = st + (uint32_t)((row * SA + c4 * 4) * 4);
                CP16(so, A + (size_t)(m0 + row) * K + k0 + c4 * 4);
                CP16(so + TBYTES, Bt + (size_t)(n0 + row) * K + k0 + c4 * 4);
            }
            CP_COMMIT();
        }
    }

#pragma unroll
    for (int mt = 0; mt < 4; mt++) {
        int r0 = m0 + wm * 64 + mt * 16 + g;
#pragma unroll
        for (int nt = 0; nt < 8; nt++) {
            int cc = n0 + wn * 64 + nt * 8 + 2 * q;
            float b0 = bias[cc], b1 = bias[cc + 1];
            float v00 = acc[mt][nt][0] + b0, v01 = acc[mt][nt][1] + b1;
            float v10 = acc[mt][nt][2] + b0, v11 = acc[mt][nt][3] + b1;
            if (mode == 0) {
                v00 = to_tf32(v00); v01 = to_tf32(v01);
                v10 = to_tf32(v10); v11 = to_tf32(v11);
            }
            *(float2*)(C + (size_t)r0 * N + cc)       = make_float2(v00, v01);
            *(float2*)(C + (size_t)(r0 + 8) * N + cc) = make_float2(v10, v11);
        }
    }
}

// ---------------------------------------------------------------------------
// Flash attention: tf32 QK^T + fp16 PV (FA2 register trick — P never touches
// smem, no barrier C). 64-query tile, 128 threads = 4 warps, double-buffered
// K (tf32) + Vt (fp16 [d][key]) tiles.
// Smem: K0|K1 (2x17408) | V0|V1 (2x9216) = 53,248 B -> 3 CTAs/SM (reg-limited).
// ---------------------------------------------------------------------------
#define SKA 68                       // K tile stride (floats)
#define KTILE_B (64 * SKA * 4)       // 17408
#define VSTRIDE 72                   // Vt stride in halves (144 B rows)
#define VTILE_B (64 * VSTRIDE * 2)   // 9216
#define AV_OFF (2 * KTILE_B)         // V buffers start
#define ASMEM (2 * KTILE_B + 2 * VTILE_B)  // 53248

__global__ __launch_bounds__(128, 3) void attn_f16pv_kernel()
{
    extern __shared__ float sm[];

    const int qt = (gridDim.x - 1) - blockIdx.x;   // heavy-first
    const int h = blockIdx.y, b = blockIdx.z;
    const int tid = threadIdx.x, lane = tid & 31, w = tid >> 5;
    const int g = lane >> 2, q = lane & 3;
    const int q0 = qt * 64;

    const uint32_t sb = smem_u32(sm);

    const size_t rs = 3 * CDIM;
    const float* qb  = g_qkv + (size_t)b * TLEN * rs + h * DH;
    const float* kb  = qb + CDIM;
    const __half* vtb = g_vt + (size_t)(b * HN + h) * DH * TLEN;

    const int lrow = tid >> 4;             // 0..7  (K/Q loads)
    const int lcol = (tid & 15) * 4;       // 0..60
    const uint32_t aoff = a_frag_off(lane, SKA);
    const uint32_t boff = b_frag_off(lane, SKA);

    // ---- preload: Q into K1 region; K tile 0 -> K0; Vt tile 0 -> V0 ----
    {
        const uint32_t sQ = sb + KTILE_B;   // K1
#pragma unroll
        for (int p = 0; p < 8; p++) {
            const uint32_t ro = (uint32_t)(((lrow + 8 * p) * SKA + lcol) * 4);
            CP16(sQ + ro, qb + (size_t)(q0 + lrow + 8 * p) * rs + lcol);
            CP16(sb + ro, kb + (size_t)(lrow + 8 * p) * rs + lcol);
        }
#pragma unroll
        for (int p = 0; p < 4; p++) {
            const int idx = tid + 128 * p;            // 0..511
            const int vr = idx >> 3, vc = idx & 7;    // row 0..63, chunk 0..7
            CP16(sb + AV_OFF + (uint32_t)(vr * 144 + vc * 16),
                 vtb + (size_t)vr * TLEN + vc * 8);
        }
        CP_COMMIT(); CP_WAIT(0);
    }
    __syncthreads();

    // hoist Q fragments, scaled by (1/sqrt(64)) * log2(e)  [base-2 softmax]
    const float QSCALE = 0.125f * 1.4426950408889634f;
    uint32_t qf[8][4];
#pragma unroll
    for (int kd = 0; kd < 8; kd++) {
        ldsm_x4(qf[kd], sb + KTILE_B + (uint32_t)(((w * 16) * SKA + kd * 8) * 4) + aoff);
#pragma unroll
        for (int e = 0; e < 4; e++)
            qf[kd][e] = __float_as_uint(__uint_as_float(qf[kd][e]) * QSCALE);
    }

    float so[8][4];
    float mrow[2] = {-1e30f, -1e30f}, lsum[2] = {0.f, 0.f};
#pragma unroll
    for (int nt = 0; nt < 8; nt++)
#pragma unroll
        for (int e = 0; e < 4; e++) so[nt][e] = 0.f;

    for (int kt = 0; kt <= qt; kt++) {
        const int p = kt & 1;
        const uint32_t sK = sb + (uint32_t)(p * KTILE_B);
        const uint32_t sV = sb + AV_OFF + (uint32_t)(p * VTILE_B);

        // barrier A: prev iter's reads of parity 1-p complete (and Q hoist at kt=0)
        __syncthreads();

        if (kt < qt) {
            const uint32_t nK = sb + (uint32_t)((1 - p) * KTILE_B);
            const uint32_t nV = sb + AV_OFF + (uint32_t)((1 - p) * VTILE_B);
            const int k0r = (kt + 1) * 64;
#pragma unroll
            for (int pp = 0; pp < 8; pp++) {
                const uint32_t ro = (uint32_t)(((lrow + 8 * pp) * SKA + lcol) * 4);
                CP16(nK + ro, kb + (size_t)(k0r + lrow + 8 * pp) * rs + lcol);
            }
#pragma unroll
            for (int pp = 0; pp < 4; pp++) {
                const int idx = tid + 128 * pp;
                const int vr = idx >> 3, vc = idx & 7;
                CP16(nV + (uint32_t)(vr * 144 + vc * 16),
                     vtb + (size_t)vr * TLEN + k0r + vc * 8);
            }
            CP_COMMIT();
            CP_WAIT(1);
        } else {
            CP_WAIT(0);
        }
        __syncthreads();    // barrier B: K_p / V_p visible to all warps

        // ---- S = Q K^T (log2 domain) ----
        float sc[8][4];
#pragma unroll
        for (int nt = 0; nt < 8; nt++)
#pragma unroll
            for (int e = 0; e < 4; e++) sc[nt][e] = 0.f;

#pragma unroll
        for (int kd = 0; kd < 8; kd++) {
            uint32_t bf[4][4];
#pragma unroll
            for (int pr = 0; pr < 4; pr++)
                ldsm_x4(bf[pr], sK + (uint32_t)(((pr * 16) * SKA + kd * 8) * 4) + boff);
#pragma unroll
            for (int nt = 0; nt < 8; nt++)
                mma_tf32(sc[nt], qf[kd], bf[nt >> 1] + (nt & 1) * 2);
        }

        // ---- causal mask on diagonal tile ----
        if (kt == qt) {
            const int r0 = w * 16 + g, r1 = r0 + 8;
#pragma unroll
            for (int nt = 0; nt < 8; nt++) {
                const int c = nt * 8 + 2 * q;
                if (c     > r0) sc[nt][0] = -1e30f;
                if (c + 1 > r0) sc[nt][1] = -1e30f;
                if (c     > r1) sc[nt][2] = -1e30f;
                if (c + 1 > r1) sc[nt][3] = -1e30f;
            }
        }

        // ---- online softmax (base-2; 2 rows per thread) ----
        float mx0 = -1e30f, mx1 = -1e30f;
#pragma unroll
        for (int nt = 0; nt < 8; nt++) {
            mx0 = fmaxf(mx0, fmaxf(sc[nt][0], sc[nt][1]));
            mx1 = fmaxf(mx1, fmaxf(sc[nt][2], sc[nt][3]));
        }
        mx0 = fmaxf(mx0, __shfl_xor_sync(0xffffffffu, mx0, 1));
        mx0 = fmaxf(mx0, __shfl_xor_sync(0xffffffffu, mx0, 2));
        mx1 = fmaxf(mx1, __shfl_xor_sync(0xffffffffu, mx1, 1));
        mx1 = fmaxf(mx1, __shfl_xor_sync(0xffffffffu, mx1, 2));

        const float mn0 = fmaxf(mrow[0], mx0);
        const float mn1 = fmaxf(mrow[1], mx1);
        const float al0 = ex2f(mrow[0] - mn0);
        const float al1 = ex2f(mrow[1] - mn1);
        mrow[0] = mn0; mrow[1] = mn1;

        float s0 = 0.f, s1 = 0.f;
#pragma unroll
        for (int nt = 0; nt < 8; nt++) {
            sc[nt][0] = ex2f(sc[nt][0] - mn0); s0 += sc[nt][0];
            sc[nt][1] = ex2f(sc[nt][1] - mn0); s0 += sc[nt][1];
            sc[nt][2] = ex2f(sc[nt][2] - mn1); s1 += sc[nt][2];
            sc[nt][3] = ex2f(sc[nt][3] - mn1); s1 += sc[nt][3];
        }
        s0 += __shfl_xor_sync(0xffffffffu, s0, 1);
        s0 += __shfl_xor_sync(0xffffffffu, s0, 2);
        s1 += __shfl_xor_sync(0xffffffffu, s1, 1);
        s1 += __shfl_xor_sync(0xffffffffu, s1, 2);
        lsum[0] = lsum[0] * al0 + s0;
        lsum[1] = lsum[1] * al1 + s1;

#pragma unroll
        for (int nt = 0; nt < 8; nt++) {
            so[nt][0] *= al0; so[nt][1] *= al0;
            so[nt][2] *= al1; so[nt][3] *= al1;
        }

        // ---- pack P to fp16 a-frags in registers (FA2 trick, no smem) ----
        uint32_t pa[4][4];
#pragma unroll
        for (int kc = 0; kc < 4; kc++) {
            pa[kc][0] = pack_f16(sc[2 * kc][0],     sc[2 * kc][1]);
            pa[kc][1] = pack_f16(sc[2 * kc][2],     sc[2 * kc][3]);
            pa[kc][2] = pack_f16(sc[2 * kc + 1][0], sc[2 * kc + 1][1]);
            pa[kc][3] = pack_f16(sc[2 * kc + 1][2], sc[2 * kc + 1][3]);
        }

        // ---- O += P V  (fp16 mma; b-frags = plain LDS.32 from Vt[d][key]) ----
        const char* vbase = (const char*)sm + p * VTILE_B + AV_OFF;
#pragma unroll
        for (int kc = 0; kc < 4; kc++) {
#pragma unroll
            for (int nt = 0; nt < 8; nt++) {
                const int row = nt * 8 + g;
                const char* vp = vbase + row * 144 + kc * 32 + q * 4;
                uint32_t bf[2];
                bf[0] = *(const uint32_t*)(vp);
                bf[1] = *(const uint32_t*)(vp + 16);
                mma_f16(so[nt], pa[kc], bf);
            }
        }
    }

    // ---- normalize + store y (tf32 for GEMM2 consumption) ----
    {
        const float inv0 = 1.f / lsum[0];
        const float inv1 = 1.f / lsum[1];
        const int r0 = q0 + w * 16 + g;
        float* yb = g_y + (size_t)b * TLEN * CDIM + h * DH;
#pragma unroll
        for (int nt = 0; nt < 8; nt++) {
            const int c = nt * 8 + 2 * q;
            *(float2*)(yb + (size_t)r0 * CDIM + c) =
                make_float2(to_tf32(so[nt][0] * inv0), to_tf32(so[nt][1] * inv0));
            *(float2*)(yb + (size_t)(r0 + 8) * CDIM + c) =
                make_float2(to_tf32(so[nt][2] * inv1), to_tf32(so[nt][3] * inv1));
        }
    }
}

// ---------------------------------------------------------------------------
extern "C" void kernel_launch(void* const* d_in, const int* in_sizes, int n_in,
                              void* d_out, int out_size)
{
    const float* x      = (const float*)d_in[0];
    const float* W_attn = (const float*)d_in[1];
    const float* b_attn = (const float*)d_in[2];
    const float* W_proj = (const float*)d_in[3];
    const float* b_proj = (const float*)d_in[4];
    float* out = (float*)d_out;

    cudaFuncSetAttribute(gemm_ls_kernel, cudaFuncAttributeMaxDynamicSharedMemorySize, GSMEM);
    cudaFuncSetAttribute(attn_f16pv_kernel, cudaFuncAttributeMaxDynamicSharedMemorySize, ASMEM);

    // 0) pre-convert x; transpose+convert weights
    cvt_kernel<<<(MROWS * CDIM) / (256 * 4), 256>>>(x);
    {
        dim3 tb(32, 8);
        transpose_kernel<<<dim3((3 * CDIM) / 32, CDIM / 32), tb>>>(W_attn, CDIM, 3 * CDIM, 0);
        transpose_kernel<<<dim3(CDIM / 32, CDIM / 32), tb>>>(W_proj, CDIM, CDIM, 1);
    }
    // 1) qkv = x @ W_attn + b_attn (tf32-rounded)
    {
        dim3 grid((3 * CDIM) / 128, MROWS / 128);
        gemm_ls_kernel<<<grid, 128, GSMEM>>>(b_attn, nullptr, MROWS, 3 * CDIM, CDIM, 0);
    }
    // 1b) transpose V slice to fp16: g_qkv -> g_vt[b,h,d,t]
    {
        dim3 tb(32, 8);
        vtrans_kernel<<<dim3(TLEN / 32, 2 * HN, BSZ), tb>>>();
    }
    // 2) flash attention (tf32 QK, fp16 PV) -> g_y
    {
        dim3 grid(TLEN / 64, HN, BSZ);
        attn_f16pv_kernel<<<grid, 128, ASMEM>>>();
    }
    // 3) out = y @ W_proj + b_proj
    {
        dim3 grid(CDIM / 128, MROWS / 128);
        gemm_ls_kernel<<<grid, 128, GSMEM>>>(b_proj, out, MROWS, CDIM, CDIM, 1);
    }
}

// round 13
// speedup vs baseline: 1.5244x; 1.2763x over previous
#include <cuda_runtime.h>
#include <cuda_fp16.h>
#include <math.h>
#include <stdint.h>

// Problem constants
#define BSZ 2
#define TLEN 2048
#define CDIM 1024
#define HN 16
#define DH 64
#define MROWS (BSZ * TLEN)   // 4096

// Scratch (allocation-free rule: __device__ globals)
__device__ float  g_qkv[(size_t)MROWS * 3 * CDIM];    // fp32 (tf32-rounded) qkv
__device__ __half g_yh[(size_t)MROWS * CDIM];         // fp16 attention output
__device__ __half g_xh[(size_t)MROWS * CDIM];         // fp16(x)
__device__ __half g_wth[(size_t)4 * CDIM * CDIM];     // fp16(W_attn^T), fp16(W_proj^T)
__device__ __half g_vt[(size_t)BSZ * HN * DH * TLEN]; // V transposed fp16: [b,h,d,t]

// ---------------------------------------------------------------------------
// helpers
// ---------------------------------------------------------------------------
__device__ __forceinline__ float to_tf32(float x) {
    uint32_t u;
    asm("cvt.rna.tf32.f32 %0, %1;" : "=r"(u) : "f"(x));
    return __uint_as_float(u);
}

__device__ __forceinline__ void mma_tf32(float* d, const uint32_t* a, const uint32_t* b) {
    asm volatile(
        "mma.sync.aligned.m16n8k8.row.col.f32.tf32.tf32.f32 "
        "{%0,%1,%2,%3}, {%4,%5,%6,%7}, {%8,%9}, {%0,%1,%2,%3};"
        : "+f"(d[0]), "+f"(d[1]), "+f"(d[2]), "+f"(d[3])
        : "r"(a[0]), "r"(a[1]), "r"(a[2]), "r"(a[3]), "r"(b[0]), "r"(b[1]));
}

__device__ __forceinline__ void mma_f16(float* d, const uint32_t* a, const uint32_t* b) {
    asm volatile(
        "mma.sync.aligned.m16n8k16.row.col.f32.f16.f16.f32 "
        "{%0,%1,%2,%3}, {%4,%5,%6,%7}, {%8,%9}, {%0,%1,%2,%3};"
        : "+f"(d[0]), "+f"(d[1]), "+f"(d[2]), "+f"(d[3])
        : "r"(a[0]), "r"(a[1]), "r"(a[2]), "r"(a[3]), "r"(b[0]), "r"(b[1]));
}

// pack two fp32 -> fp16x2 reg (lo = low half)
__device__ __forceinline__ uint32_t pack_f16(float lo, float hi) {
    uint32_t r;
    asm("cvt.rn.f16x2.f32 %0, %1, %2;" : "=r"(r) : "f"(hi), "f"(lo));
    return r;
}

__device__ __forceinline__ float ex2f(float x) {
    float r;
    asm("ex2.approx.f32 %0, %1;" : "=f"(r) : "f"(x));
    return r;
}

__device__ __forceinline__ uint32_t smem_u32(const void* p) {
    uint32_t a;
    asm("{ .reg .u64 t; cvta.to.shared.u64 t, %1; cvt.u32.u64 %0, t; }"
        : "=r"(a) : "l"(p));
    return a;
}

__device__ __forceinline__ void ldsm_x4(uint32_t* r, uint32_t addr) {
    asm volatile("ldmatrix.sync.aligned.m8n8.x4.shared.b16 {%0,%1,%2,%3}, [%4];"
                 : "=r"(r[0]), "=r"(r[1]), "=r"(r[2]), "=r"(r[3]) : "r"(addr));
}

// tf32 (4-byte) fragment offsets, stride in floats
__device__ __forceinline__ uint32_t a_frag_off(int lane, int stride) {
    int mat = lane >> 3, rw = lane & 7;
    return (uint32_t)(((8 * (mat & 1) + rw) * stride + 4 * (mat >> 1)) * 4);
}
__device__ __forceinline__ uint32_t b_frag_off(int lane, int stride) {
    int mat = lane >> 3, rw = lane & 7;
    return (uint32_t)(((8 * (mat >> 1) + rw) * stride + 4 * (mat & 1)) * 4);
}
// fp16 (2-byte) fragment offsets, stride in halves. 8x8 b16 matrix = 8 rows x 16B.
// a mats: (mlo,klo),(mhi,klo),(mlo,khi),(mhi,khi); b mats: (nlo,klo),(nlo,khi),(nhi,klo),(nhi,khi)
__device__ __forceinline__ uint32_t a_frag_off16(int lane, int stride) {
    int mat = lane >> 3, rw = lane & 7;
    return (uint32_t)(((8 * (mat & 1) + rw) * stride + 8 * (mat >> 1)) * 2);
}
__device__ __forceinline__ uint32_t b_frag_off16(int lane, int stride) {
    int mat = lane >> 3, rw = lane & 7;
    return (uint32_t)(((8 * (mat >> 1) + rw) * stride + 8 * (mat & 1)) * 2);
}

#define CP16(s, g) \
    asm volatile("cp.async.cg.shared.global [%0], [%1], 16;" :: "r"(s), "l"(g) : "memory")
#define CP_COMMIT() asm volatile("cp.async.commit_group;" ::: "memory")
#define CP_WAIT(n)  asm volatile("cp.async.wait_group %0;" :: "n"(n) : "memory")

// ---------------------------------------------------------------------------
// x -> fp16 conversion
// ---------------------------------------------------------------------------
__global__ __launch_bounds__(256) void cvt_kernel(const float* __restrict__ x)
{
    size_t i = ((size_t)blockIdx.x * 256 + threadIdx.x) * 4;
    float4 v = *(const float4*)(x + i);
    uint2 o;
    o.x = pack_f16(v.x, v.y);
    o.y = pack_f16(v.z, v.w);
    *(uint2*)(g_xh + i) = o;
}

// ---------------------------------------------------------------------------
// Weight transpose + fp16: src[K][N] -> g_wth(+off)[N][K]
// ---------------------------------------------------------------------------
__global__ __launch_bounds__(256) void transpose_kernel(
    const float* __restrict__ src, int K, int N, int sel)
{
    __shared__ float t[32][33];
    __half* dst = g_wth + (sel ? (size_t)3 * CDIM * CDIM : 0);
    const int nb = blockIdx.x * 32, kb = blockIdx.y * 32;
    const int x = threadIdx.x, y = threadIdx.y;
#pragma unroll
    for (int j = 0; j < 32; j += 8)
        t[y + j][x] = src[(size_t)(kb + y + j) * N + nb + x];
    __syncthreads();
#pragma unroll
    for (int j = 0; j < 32; j += 8)
        dst[(size_t)(nb + y + j) * K + kb + x] = __float2half(t[x][y + j]);
}

// ---------------------------------------------------------------------------
// V transpose to fp16: g_qkv V slice [b,t,(h,d)] -> g_vt[b,h,d,t]
// ---------------------------------------------------------------------------
__global__ __launch_bounds__(256) void vtrans_kernel()
{
    __shared__ float t[32][33];
    const int b = blockIdx.z;
    const int h = blockIdx.y >> 1;
    const int d0 = (blockIdx.y & 1) * 32;
    const int t0 = blockIdx.x * 32;
    const int x = threadIdx.x, y = threadIdx.y;

    const float* src = g_qkv + (size_t)b * TLEN * 3 * CDIM + 2 * CDIM + h * DH;
#pragma unroll
    for (int j = 0; j < 32; j += 8)
        t[y + j][x] = src[(size_t)(t0 + y + j) * 3 * CDIM + d0 + x];
    __syncthreads();
    __half* dst = g_vt + ((size_t)(b * HN + h) * DH + d0) * TLEN + t0;
#pragma unroll
    for (int j = 0; j < 32; j += 8)
        dst[(size_t)(y + j) * TLEN + x] = __float2half(t[x][y + j]);
}

// ---------------------------------------------------------------------------
// fp16 GEMM (m16n8k16): C[M,N] = A[M,K] @ W[K,N] + bias[N], fp32 accumulate.
// 128x128 tile, 128 threads = 4 warps (2m x 2n), warp tile 64x64, BK=32,
// 2-stage cp.async ring (40,960 B), 3 CTAs/SM.
// mode 0: A=g_xh, C=g_qkv (fp32, tf32-rounded); mode 1: A=g_yh, C=C_param.
// ---------------------------------------------------------------------------
#define SH 40                        // smem stride (halves); 80B rows, LDSM conflict-free
#define HTILE_B (128 * SH * 2)       // 10240 per tile (A or B)
#define HSTAGE (2 * HTILE_B)         // 20480 per stage
#define HGSMEM (2 * HSTAGE)          // 40960

__global__ __launch_bounds__(128, 3) void gemm_h_kernel(
    const float* __restrict__ bias, float* __restrict__ C_param,
    int M, int N, int K, int mode)
{
    extern __shared__ char smh[];
    const __half* A  = mode ? g_yh : g_xh;
    const __half* Bt = g_wth + (mode ? (size_t)3 * CDIM * CDIM : 0);
    float*        C  = mode ? C_param : g_qkv;

    const int tid = threadIdx.x, lane = tid & 31, wid = tid >> 5;
    const int wm = wid >> 1, wn = wid & 1;
    const int g = lane >> 2, q = lane & 3;
    const int m0 = blockIdx.y * 128, n0 = blockIdx.x * 128;
    const uint32_t sb = smem_u32(smh);

    const uint32_t a_off = a_frag_off16(lane, SH);
    const uint32_t b_off = b_frag_off16(lane, SH);

    float acc[4][8][4];
#pragma unroll
    for (int mt = 0; mt < 4; mt++)
#pragma unroll
        for (int nt = 0; nt < 8; nt++)
#pragma unroll
            for (int e = 0; e < 4; e++) acc[mt][nt][e] = 0.f;

    const int nc = K / 32;

    // prefetch stages 0 and 1 (per stage: 512 chunks A + 512 chunks B, 8/thread)
#pragma unroll
    for (int s = 0; s < 2; s++) {
        const int k0 = s * 32;
        const uint32_t st = sb + (uint32_t)(s * HSTAGE);
#pragma unroll
        for (int i = 0; i < 4; i++) {
            const int f = tid + 128 * i;          // 0..511
            const int row = f >> 2, c4 = f & 3;
            const uint32_t so = st + (uint32_t)(row * (SH * 2) + c4 * 16);
            CP16(so, A + (size_t)(m0 + row) * K + k0 + c4 * 8);
            CP16(so + HTILE_B, Bt + (size_t)(n0 + row) * K + k0 + c4 * 8);
        }
        CP_COMMIT();
    }

    for (int c = 0; c < nc; c++) {
        if (c == nc - 1) { CP_WAIT(0); } else { CP_WAIT(1); }
        __syncthreads();

        const uint32_t ab = sb + (uint32_t)((c & 1) * HSTAGE);
        const uint32_t bbse = ab + HTILE_B;
#pragma unroll
        for (int kk = 0; kk < 32; kk += 16) {
            uint32_t af[4][4], bf[4][4];
#pragma unroll
            for (int mt = 0; mt < 4; mt++)
                ldsm_x4(af[mt], ab + (uint32_t)(((wm * 64 + mt * 16) * SH + kk) * 2) + a_off);
#pragma unroll
            for (int pr = 0; pr < 4; pr++)
                ldsm_x4(bf[pr], bbse + (uint32_t)(((wn * 64 + pr * 16) * SH + kk) * 2) + b_off);
#pragma unroll
            for (int mt = 0; mt < 4; mt++)
#pragma unroll
                for (int nt = 0; nt < 8; nt++)
                    mma_f16(acc[mt][nt], af[mt], bf[nt >> 1] + (nt & 1) * 2);
        }
        __syncthreads();

        if (c + 2 < nc) {
            const int k0 = (c + 2) * 32;
            const uint32_t st = sb + (uint32_t)((c & 1) * HSTAGE);
#pragma unroll
            for (int i = 0; i < 4; i++) {
                const int f = tid + 128 * i;
                const int row = f >> 2, c4 = f & 3;
                const uint32_t so = st + (uint32_t)(row * (SH * 2) + c4 * 16);
                CP16(so, A + (size_t)(m0 + row) * K + k0 + c4 * 8);
                CP16(so + HTILE_B, Bt + (size_t)(n0 + row) * K + k0 + c4 * 8);
            }
            CP_COMMIT();
        }
    }

    // epilogue: bias + fp32 store (tf32-rounded for qkv so QK path is unchanged)
#pragma unroll
    for (int mt = 0; mt < 4; mt++) {
        int r0 = m0 + wm * 64 + mt * 16 + g;
#pragma unroll
        for (int nt = 0; nt < 8; nt++) {
            int cc = n0 + wn * 64 + nt * 8 + 2 * q;
            float b0 = bias[cc], b1 = bias[cc + 1];
            float v00 = acc[mt][nt][0] + b0, v01 = acc[mt][nt][1] + b1;
            float v10 = acc[mt][nt][2] + b0, v11 = acc[mt][nt][3] + b1;
            if (mode == 0) {
                v00 = to_tf32(v00); v01 = to_tf32(v01);
                v10 = to_tf32(v10); v11 = to_tf32(v11);
            }
            *(float2*)(C + (size_t)r0 * N + cc)       = make_float2(v00, v01);
            *(float2*)(C + (size_t)(r0 + 8) * N + cc) = make_float2(v10, v11);
        }
    }
}

// ---------------------------------------------------------------------------
// Flash attention: tf32 QK^T + fp16 PV (FA2 register trick), unchanged from
// R12 except y is stored fp16 (g_yh) for the fp16 GEMM2.
// ---------------------------------------------------------------------------
#define SKA 68                       // K tile stride (floats)
#define KTILE_B (64 * SKA * 4)       // 17408
#define VSTRIDE 72                   // Vt stride in halves (144 B rows)
#define VTILE_B (64 * VSTRIDE * 2)   // 9216
#define AV_OFF (2 * KTILE_B)
#define ASMEM (2 * KTILE_B + 2 * VTILE_B)  // 53248

__global__ __launch_bounds__(128, 3) void attn_f16pv_kernel()
{
    extern __shared__ float sm[];

    const int qt = (gridDim.x - 1) - blockIdx.x;   // heavy-first
    const int h = blockIdx.y, b = blockIdx.z;
    const int tid = threadIdx.x, lane = tid & 31, w = tid >> 5;
    const int g = lane >> 2, q = lane & 3;
    const int q0 = qt * 64;

    const uint32_t sb = smem_u32(sm);

    const size_t rs = 3 * CDIM;
    const float* qb  = g_qkv + (size_t)b * TLEN * rs + h * DH;
    const float* kb  = qb + CDIM;
    const __half* vtb = g_vt + (size_t)(b * HN + h) * DH * TLEN;

    const int lrow = tid >> 4;
    const int lcol = (tid & 15) * 4;
    const uint32_t aoff = a_frag_off(lane, SKA);
    const uint32_t boff = b_frag_off(lane, SKA);

    // ---- preload: Q into K1 region; K tile 0 -> K0; Vt tile 0 -> V0 ----
    {
        const uint32_t sQ = sb + KTILE_B;
#pragma unroll
        for (int p = 0; p < 8; p++) {
            const uint32_t ro = (uint32_t)(((lrow + 8 * p) * SKA + lcol) * 4);
            CP16(sQ + ro, qb + (size_t)(q0 + lrow + 8 * p) * rs + lcol);
            CP16(sb + ro, kb + (size_t)(lrow + 8 * p) * rs + lcol);
        }
#pragma unroll
        for (int p = 0; p < 4; p++) {
            const int idx = tid + 128 * p;
            const int vr = idx >> 3, vc = idx & 7;
            CP16(sb + AV_OFF + (uint32_t)(vr * 144 + vc * 16),
                 vtb + (size_t)vr * TLEN + vc * 8);
        }
        CP_COMMIT(); CP_WAIT(0);
    }
    __syncthreads();

    // hoist Q fragments, scaled by (1/sqrt(64)) * log2(e)
    const float QSCALE = 0.125f * 1.4426950408889634f;
    uint32_t qf[8][4];
#pragma unroll
    for (int kd = 0; kd < 8; kd++) {
        ldsm_x4(qf[kd], sb + KTILE_B + (uint32_t)(((w * 16) * SKA + kd * 8) * 4) + aoff);
#pragma unroll
        for (int e = 0; e < 4; e++)
            qf[kd][e] = __float_as_uint(__uint_as_float(qf[kd][e]) * QSCALE);
    }

    float so[8][4];
    float mrow[2] = {-1e30f, -1e30f}, lsum[2] = {0.f, 0.f};
#pragma unroll
    for (int nt = 0; nt < 8; nt++)
#pragma unroll
        for (int e = 0; e < 4; e++) so[nt][e] = 0.f;

    for (int kt = 0; kt <= qt; kt++) {
        const int p = kt & 1;
        const uint32_t sK = sb + (uint32_t)(p * KTILE_B);

        __syncthreads();   // barrier A

        if (kt < qt) {
            const uint32_t nK = sb + (uint32_t)((1 - p) * KTILE_B);
            const uint32_t nV = sb + AV_OFF + (uint32_t)((1 - p) * VTILE_B);
            const int k0r = (kt + 1) * 64;
#pragma unroll
            for (int pp = 0; pp < 8; pp++) {
                const uint32_t ro = (uint32_t)(((lrow + 8 * pp) * SKA + lcol) * 4);
                CP16(nK + ro, kb + (size_t)(k0r + lrow + 8 * pp) * rs + lcol);
            }
#pragma unroll
            for (int pp = 0; pp < 4; pp++) {
                const int idx = tid + 128 * pp;
                const int vr = idx >> 3, vc = idx & 7;
                CP16(nV + (uint32_t)(vr * 144 + vc * 16),
                     vtb + (size_t)vr * TLEN + k0r + vc * 8);
            }
            CP_COMMIT();
            CP_WAIT(1);
        } else {
            CP_WAIT(0);
        }
        __syncthreads();    // barrier B

        // ---- S = Q K^T (log2 domain) ----
        float sc[8][4];
#pragma unroll
        for (int nt = 0; nt < 8; nt++)
#pragma unroll
            for (int e = 0; e < 4; e++) sc[nt][e] = 0.f;

#pragma unroll
        for (int kd = 0; kd < 8; kd++) {
            uint32_t bf[4][4];
#pragma unroll
            for (int pr = 0; pr < 4; pr++)
                ldsm_x4(bf[pr], sK + (uint32_t)(((pr * 16) * SKA + kd * 8) * 4) + boff);
#pragma unroll
            for (int nt = 0; nt < 8; nt++)
                mma_tf32(sc[nt], qf[kd], bf[nt >> 1] + (nt & 1) * 2);
        }

        // ---- causal mask on diagonal tile ----
        if (kt == qt) {
            const int r0 = w * 16 + g, r1 = r0 + 8;
#pragma unroll
            for (int nt = 0; nt < 8; nt++) {
                const int c = nt * 8 + 2 * q;
                if (c     > r0) sc[nt][0] = -1e30f;
                if (c + 1 > r0) sc[nt][1] = -1e30f;
                if (c     > r1) sc[nt][2] = -1e30f;
                if (c + 1 > r1) sc[nt][3] = -1e30f;
            }
        }

        // ---- online softmax (base-2) ----
        float mx0 = -1e30f, mx1 = -1e30f;
#pragma unroll
        for (int nt = 0; nt < 8; nt++) {
            mx0 = fmaxf(mx0, fmaxf(sc[nt][0], sc[nt][1]));
            mx1 = fmaxf(mx1, fmaxf(sc[nt][2], sc[nt][3]));
        }
        mx0 = fmaxf(mx0, __shfl_xor_sync(0xffffffffu, mx0, 1));
        mx0 = fmaxf(mx0, __shfl_xor_sync(0xffffffffu, mx0, 2));
        mx1 = fmaxf(mx1, __shfl_xor_sync(0xffffffffu, mx1, 1));
        mx1 = fmaxf(mx1, __shfl_xor_sync(0xffffffffu, mx1, 2));

        const float mn0 = fmaxf(mrow[0], mx0);
        const float mn1 = fmaxf(mrow[1], mx1);
        const float al0 = ex2f(mrow[0] - mn0);
        const float al1 = ex2f(mrow[1] - mn1);
        mrow[0] = mn0; mrow[1] = mn1;

        float s0 = 0.f, s1 = 0.f;
#pragma unroll
        for (int nt = 0; nt < 8; nt++) {
            sc[nt][0] = ex2f(sc[nt][0] - mn0); s0 += sc[nt][0];
            sc[nt][1] = ex2f(sc[nt][1] - mn0); s0 += sc[nt][1];
            sc[nt][2] = ex2f(sc[nt][2] - mn1); s1 += sc[nt][2];
            sc[nt][3] = ex2f(sc[nt][3] - mn1); s1 += sc[nt][3];
        }
        s0 += __shfl_xor_sync(0xffffffffu, s0, 1);
        s0 += __shfl_xor_sync(0xffffffffu, s0, 2);
        s1 += __shfl_xor_sync(0xffffffffu, s1, 1);
        s1 += __shfl_xor_sync(0xffffffffu, s1, 2);
        lsum[0] = lsum[0] * al0 + s0;
        lsum[1] = lsum[1] * al1 + s1;

#pragma unroll
        for (int nt = 0; nt < 8; nt++) {
            so[nt][0] *= al0; so[nt][1] *= al0;
            so[nt][2] *= al1; so[nt][3] *= al1;
        }

        // ---- pack P to fp16 a-frags in registers ----
        uint32_t pa[4][4];
#pragma unroll
        for (int kc = 0; kc < 4; kc++) {
            pa[kc][0] = pack_f16(sc[2 * kc][0],     sc[2 * kc][1]);
            pa[kc][1] = pack_f16(sc[2 * kc][2],     sc[2 * kc][3]);
            pa[kc][2] = pack_f16(sc[2 * kc + 1][0], sc[2 * kc + 1][1]);
            pa[kc][3] = pack_f16(sc[2 * kc + 1][2], sc[2 * kc + 1][3]);
        }

        // ---- O += P V ----
        const char* vbase = (const char*)sm + p * VTILE_B + AV_OFF;
#pragma unroll
        for (int kc = 0; kc < 4; kc++) {
#pragma unroll
            for (int nt = 0; nt < 8; nt++) {
                const int row = nt * 8 + g;
                const char* vp = vbase + row * 144 + kc * 32 + q * 4;
                uint32_t bf[2];
                bf[0] = *(const uint32_t*)(vp);
                bf[1] = *(const uint32_t*)(vp + 16);
                mma_f16(so[nt], pa[kc], bf);
            }
        }
    }

    // ---- normalize + store y as fp16 (for fp16 GEMM2) ----
    {
        const float inv0 = 1.f / lsum[0];
        const float inv1 = 1.f / lsum[1];
        const int r0 = q0 + w * 16 + g;
        __half* yb = g_yh + (size_t)b * TLEN * CDIM + h * DH;
#pragma unroll
        for (int nt = 0; nt < 8; nt++) {
            const int c = nt * 8 + 2 * q;
            *(uint32_t*)(yb + (size_t)r0 * CDIM + c) =
                pack_f16(so[nt][0] * inv0, so[nt][1] * inv0);
            *(uint32_t*)(yb + (size_t)(r0 + 8) * CDIM + c) =
                pack_f16(so[nt][2] * inv1, so[nt][3] * inv1);
        }
    }
}

// ---------------------------------------------------------------------------
extern "C" void kernel_launch(void* const* d_in, const int* in_sizes, int n_in,
                              void* d_out, int out_size)
{
    const float* x      = (const float*)d_in[0];
    const float* W_attn = (const float*)d_in[1];
    const float* b_attn = (const float*)d_in[2];
    const float* W_proj = (const float*)d_in[3];
    const float* b_proj = (const float*)d_in[4];
    float* out = (float*)d_out;

    cudaFuncSetAttribute(gemm_h_kernel, cudaFuncAttributeMaxDynamicSharedMemorySize, HGSMEM);
    cudaFuncSetAttribute(attn_f16pv_kernel, cudaFuncAttributeMaxDynamicSharedMemorySize, ASMEM);

    // 0) pre-convert x; transpose+convert weights (fp16)
    cvt_kernel<<<(MROWS * CDIM) / (256 * 4), 256>>>(x);
    {
        dim3 tb(32, 8);
        transpose_kernel<<<dim3((3 * CDIM) / 32, CDIM / 32), tb>>>(W_attn, CDIM, 3 * CDIM, 0);
        transpose_kernel<<<dim3(CDIM / 32, CDIM / 32), tb>>>(W_proj, CDIM, CDIM, 1);
    }
    // 1) qkv = x @ W_attn + b_attn (fp16 inputs, fp32 accum, tf32-rounded store)
    {
        dim3 grid((3 * CDIM) / 128, MROWS / 128);
        gemm_h_kernel<<<grid, 128, HGSMEM>>>(b_attn, nullptr, MROWS, 3 * CDIM, CDIM, 0);
    }
    // 1b) transpose V slice to fp16: g_qkv -> g_vt[b,h,d,t]
    {
        dim3 tb(32, 8);
        vtrans_kernel<<<dim3(TLEN / 32, 2 * HN, BSZ), tb>>>();
    }
    // 2) flash attention (tf32 QK, fp16 PV) -> g_yh
    {
        dim3 grid(TLEN / 64, HN, BSZ);
        attn_f16pv_kernel<<<grid, 128, ASMEM>>>();
    }
    // 3) out = y @ W_proj + b_proj (fp16 inputs, fp32 accum + store)
    {
        dim3 grid(CDIM / 128, MROWS / 128);
        gemm_h_kernel<<<grid, 128, HGSMEM>>>(b_proj, out, MROWS, CDIM, CDIM, 1);
    }
}

// round 14
// speedup vs baseline: 1.7866x; 1.1720x over previous
#include <cuda_runtime.h>
#include <cuda_fp16.h>
#include <math.h>
#include <stdint.h>

// Problem constants
#define BSZ 2
#define TLEN 2048
#define CDIM 1024
#define HN 16
#define DH 64
#define MROWS (BSZ * TLEN)   // 4096

// Scratch (allocation-free rule: __device__ globals)
__device__ __half g_qkvh[(size_t)MROWS * 3 * CDIM];   // fp16 qkv [B,T,3C]
__device__ __half g_yh[(size_t)MROWS * CDIM];         // fp16 attention output
__device__ __half g_xh[(size_t)MROWS * CDIM];         // fp16(x)
__device__ __half g_wth[(size_t)4 * CDIM * CDIM];     // fp16(W_attn^T), fp16(W_proj^T)
__device__ __half g_vt[(size_t)BSZ * HN * DH * TLEN]; // V transposed fp16: [b,h,d,t]

// ---------------------------------------------------------------------------
// helpers
// ---------------------------------------------------------------------------
__device__ __forceinline__ void mma_f16(float* d, const uint32_t* a, const uint32_t* b) {
    asm volatile(
        "mma.sync.aligned.m16n8k16.row.col.f32.f16.f16.f32 "
        "{%0,%1,%2,%3}, {%4,%5,%6,%7}, {%8,%9}, {%0,%1,%2,%3};"
        : "+f"(d[0]), "+f"(d[1]), "+f"(d[2]), "+f"(d[3])
        : "r"(a[0]), "r"(a[1]), "r"(a[2]), "r"(a[3]), "r"(b[0]), "r"(b[1]));
}

// pack two fp32 -> fp16x2 reg (lo = low half)
__device__ __forceinline__ uint32_t pack_f16(float lo, float hi) {
    uint32_t r;
    asm("cvt.rn.f16x2.f32 %0, %1, %2;" : "=r"(r) : "f"(hi), "f"(lo));
    return r;
}

// scale a fp16x2 reg by fp32 s (unpack -> fp32 mul -> repack; unbiased)
__device__ __forceinline__ uint32_t scale_h2(uint32_t v, float s) {
    __half2 h = *(__half2*)&v;
    float lo = __low2float(h) * s;
    float hi = __high2float(h) * s;
    return pack_f16(lo, hi);
}

__device__ __forceinline__ float ex2f(float x) {
    float r;
    asm("ex2.approx.f32 %0, %1;" : "=f"(r) : "f"(x));
    return r;
}

__device__ __forceinline__ uint32_t smem_u32(const void* p) {
    uint32_t a;
    asm("{ .reg .u64 t; cvta.to.shared.u64 t, %1; cvt.u32.u64 %0, t; }"
        : "=r"(a) : "l"(p));
    return a;
}

__device__ __forceinline__ void ldsm_x4(uint32_t* r, uint32_t addr) {
    asm volatile("ldmatrix.sync.aligned.m8n8.x4.shared.b16 {%0,%1,%2,%3}, [%4];"
                 : "=r"(r[0]), "=r"(r[1]), "=r"(r[2]), "=r"(r[3]) : "r"(addr));
}

// fp16 (2-byte) fragment offsets, stride in halves.
// a mats: (mlo,klo),(mhi,klo),(mlo,khi),(mhi,khi); b mats: (nlo,klo),(nlo,khi),(nhi,klo),(nhi,khi)
__device__ __forceinline__ uint32_t a_frag_off16(int lane, int stride) {
    int mat = lane >> 3, rw = lane & 7;
    return (uint32_t)(((8 * (mat & 1) + rw) * stride + 8 * (mat >> 1)) * 2);
}
__device__ __forceinline__ uint32_t b_frag_off16(int lane, int stride) {
    int mat = lane >> 3, rw = lane & 7;
    return (uint32_t)(((8 * (mat >> 1) + rw) * stride + 8 * (mat & 1)) * 2);
}

#define CP16(s, g) \
    asm volatile("cp.async.cg.shared.global [%0], [%1], 16;" :: "r"(s), "l"(g) : "memory")
#define CP_COMMIT() asm volatile("cp.async.commit_group;" ::: "memory")
#define CP_WAIT(n)  asm volatile("cp.async.wait_group %0;" :: "n"(n) : "memory")

// ---------------------------------------------------------------------------
// x -> fp16 conversion
// ---------------------------------------------------------------------------
__global__ __launch_bounds__(256) void cvt_kernel(const float* __restrict__ x)
{
    size_t i = ((size_t)blockIdx.x * 256 + threadIdx.x) * 4;
    float4 v = *(const float4*)(x + i);
    uint2 o;
    o.x = pack_f16(v.x, v.y);
    o.y = pack_f16(v.z, v.w);
    *(uint2*)(g_xh + i) = o;
}

// ---------------------------------------------------------------------------
// Weight transpose + fp16: src[K][N] -> g_wth(+off)[N][K]
// ---------------------------------------------------------------------------
__global__ __launch_bounds__(256) void transpose_kernel(
    const float* __restrict__ src, int K, int N, int sel)
{
    __shared__ float t[32][33];
    __half* dst = g_wth + (sel ? (size_t)3 * CDIM * CDIM : 0);
    const int nb = blockIdx.x * 32, kb = blockIdx.y * 32;
    const int x = threadIdx.x, y = threadIdx.y;
#pragma unroll
    for (int j = 0; j < 32; j += 8)
        t[y + j][x] = src[(size_t)(kb + y + j) * N + nb + x];
    __syncthreads();
#pragma unroll
    for (int j = 0; j < 32; j += 8)
        dst[(size_t)(nb + y + j) * K + kb + x] = __float2half(t[x][y + j]);
}

// ---------------------------------------------------------------------------
// V transpose: g_qkvh V slice [b,t,(h,d)] fp16 -> g_vt[b,h,d,t] fp16
// ---------------------------------------------------------------------------
__global__ __launch_bounds__(256) void vtrans_kernel()
{
    __shared__ __half t[32][36];
    const int b = blockIdx.z;
    const int h = blockIdx.y >> 1;
    const int d0 = (blockIdx.y & 1) * 32;
    const int t0 = blockIdx.x * 32;
    const int x = threadIdx.x, y = threadIdx.y;

    const __half* src = g_qkvh + (size_t)b * TLEN * 3 * CDIM + 2 * CDIM + h * DH;
#pragma unroll
    for (int j = 0; j < 32; j += 8)
        t[y + j][x] = src[(size_t)(t0 + y + j) * 3 * CDIM + d0 + x];
    __syncthreads();
    __half* dst = g_vt + ((size_t)(b * HN + h) * DH + d0) * TLEN + t0;
#pragma unroll
    for (int j = 0; j < 32; j += 8)
        dst[(size_t)(y + j) * TLEN + x] = t[x][y + j];
}

// ---------------------------------------------------------------------------
// fp16 GEMM (m16n8k16): C[M,N] = A[M,K] @ W[K,N] + bias[N], fp32 accumulate.
// 128x128 tile, 128 threads = 4 warps (2m x 2n), warp tile 64x64, BK=32,
// 2-stage cp.async ring, 3 CTAs/SM.
// mode 0: A=g_xh, C=g_qkvh (fp16); mode 1: A=g_yh, C=C_param (fp32).
// ---------------------------------------------------------------------------
#define SH 40                        // smem stride (halves); 80B rows, LDSM conflict-free
#define HTILE_B (128 * SH * 2)       // 10240 per tile (A or B)
#define HSTAGE (2 * HTILE_B)         // 20480 per stage
#define HGSMEM (2 * HSTAGE)          // 40960

__global__ __launch_bounds__(128, 3) void gemm_h_kernel(
    const float* __restrict__ bias, float* __restrict__ C_param,
    int M, int N, int K, int mode)
{
    extern __shared__ char smh[];
    const __half* A  = mode ? g_yh : g_xh;
    const __half* Bt = g_wth + (mode ? (size_t)3 * CDIM * CDIM : 0);

    const int tid = threadIdx.x, lane = tid & 31, wid = tid >> 5;
    const int wm = wid >> 1, wn = wid & 1;
    const int g = lane >> 2, q = lane & 3;
    const int m0 = blockIdx.y * 128, n0 = blockIdx.x * 128;
    const uint32_t sb = smem_u32(smh);

    const uint32_t a_off = a_frag_off16(lane, SH);
    const uint32_t b_off = b_frag_off16(lane, SH);

    float acc[4][8][4];
#pragma unroll
    for (int mt = 0; mt < 4; mt++)
#pragma unroll
        for (int nt = 0; nt < 8; nt++)
#pragma unroll
            for (int e = 0; e < 4; e++) acc[mt][nt][e] = 0.f;

    const int nc = K / 32;

#pragma unroll
    for (int s = 0; s < 2; s++) {
        const int k0 = s * 32;
        const uint32_t st = sb + (uint32_t)(s * HSTAGE);
#pragma unroll
        for (int i = 0; i < 4; i++) {
            const int f = tid + 128 * i;          // 0..511
            const int row = f >> 2, c4 = f & 3;
            const uint32_t so = st + (uint32_t)(row * (SH * 2) + c4 * 16);
            CP16(so, A + (size_t)(m0 + row) * K + k0 + c4 * 8);
            CP16(so + HTILE_B, Bt + (size_t)(n0 + row) * K + k0 + c4 * 8);
        }
        CP_COMMIT();
    }

    for (int c = 0; c < nc; c++) {
        if (c == nc - 1) { CP_WAIT(0); } else { CP_WAIT(1); }
        __syncthreads();

        const uint32_t ab = sb + (uint32_t)((c & 1) * HSTAGE);
        const uint32_t bbse = ab + HTILE_B;
#pragma unroll
        for (int kk = 0; kk < 32; kk += 16) {
            uint32_t af[4][4], bf[4][4];
#pragma unroll
            for (int mt = 0; mt < 4; mt++)
                ldsm_x4(af[mt], ab + (uint32_t)(((wm * 64 + mt * 16) * SH + kk) * 2) + a_off);
#pragma unroll
            for (int pr = 0; pr < 4; pr++)
                ldsm_x4(bf[pr], bbse + (uint32_t)(((wn * 64 + pr * 16) * SH + kk) * 2) + b_off);
#pragma unroll
            for (int mt = 0; mt < 4; mt++)
#pragma unroll
                for (int nt = 0; nt < 8; nt++)
                    mma_f16(acc[mt][nt], af[mt], bf[nt >> 1] + (nt & 1) * 2);
        }
        __syncthreads();

        if (c + 2 < nc) {
            const int k0 = (c + 2) * 32;
            const uint32_t st = sb + (uint32_t)((c & 1) * HSTAGE);
#pragma unroll
            for (int i = 0; i < 4; i++) {
                const int f = tid + 128 * i;
                const int row = f >> 2, c4 = f & 3;
                const uint32_t so = st + (uint32_t)(row * (SH * 2) + c4 * 16);
                CP16(so, A + (size_t)(m0 + row) * K + k0 + c4 * 8);
                CP16(so + HTILE_B, Bt + (size_t)(n0 + row) * K + k0 + c4 * 8);
            }
            CP_COMMIT();
        }
    }

    // epilogue: bias (fp32), then fp16 store (mode 0 -> g_qkvh) or fp32 (mode 1)
#pragma unroll
    for (int mt = 0; mt < 4; mt++) {
        int r0 = m0 + wm * 64 + mt * 16 + g;
#pragma unroll
        for (int nt = 0; nt < 8; nt++) {
            int cc = n0 + wn * 64 + nt * 8 + 2 * q;
            float b0 = bias[cc], b1 = bias[cc + 1];
            float v00 = acc[mt][nt][0] + b0, v01 = acc[mt][nt][1] + b1;
            float v10 = acc[mt][nt][2] + b0, v11 = acc[mt][nt][3] + b1;
            if (mode == 0) {
                *(uint32_t*)(g_qkvh + (size_t)r0 * N + cc)       = pack_f16(v00, v01);
                *(uint32_t*)(g_qkvh + (size_t)(r0 + 8) * N + cc) = pack_f16(v10, v11);
            } else {
                *(float2*)(C_param + (size_t)r0 * N + cc)       = make_float2(v00, v01);
                *(float2*)(C_param + (size_t)(r0 + 8) * N + cc) = make_float2(v10, v11);
            }
        }
    }
}

// ---------------------------------------------------------------------------
// Flash attention, all-fp16 MMA: fp16 QK^T (m16n8k16) + fp16 PV (FA2 register
// trick). 64-query tile, 128 threads = 4 warps, double-buffered K/V.
// Smem: K0|K1|V0|V1, each 64 rows x 72 halves = 9,216 B -> 36,864 B total.
// Q stages through K1 before the pipeline; fragments hoisted + fp32-scaled.
// ---------------------------------------------------------------------------
#define AST 72                       // K/V tile stride (halves); 144 B rows, conflict-free
#define ATILE_B (64 * AST * 2)       // 9216
#define ASMEM (4 * ATILE_B)          // 36864

__global__ __launch_bounds__(128, 3) void attn_h_kernel()
{
    extern __shared__ char sma[];

    const int qt = (gridDim.x - 1) - blockIdx.x;   // heavy-first
    const int h = blockIdx.y, b = blockIdx.z;
    const int tid = threadIdx.x, lane = tid & 31, w = tid >> 5;
    const int g = lane >> 2, q = lane & 3;
    const int q0 = qt * 64;

    const uint32_t sb = smem_u32(sma);

    const size_t rs = 3 * CDIM;
    const __half* qb  = g_qkvh + (size_t)b * TLEN * rs + h * DH;
    const __half* kb  = qb + CDIM;
    const __half* vtb = g_vt + (size_t)(b * HN + h) * DH * TLEN;

    // tile load mapping: 64 rows x 8 chunks(16B); thread covers 4 chunks
    const uint32_t aoff = a_frag_off16(lane, AST);
    const uint32_t boff = b_frag_off16(lane, AST);

    // ---- preload: Q -> K1 region; K tile 0 -> K0; Vt tile 0 -> V0 ----
    {
        const uint32_t sQ = sb + ATILE_B;
#pragma unroll
        for (int p = 0; p < 4; p++) {
            const int idx = tid + 128 * p;            // 0..511
            const int r = idx >> 3, c = idx & 7;
            const uint32_t ro = (uint32_t)(r * (AST * 2) + c * 16);
            CP16(sQ + ro, qb + (size_t)(q0 + r) * rs + c * 8);
            CP16(sb + ro, kb + (size_t)r * rs + c * 8);
            CP16(sb + 2 * ATILE_B + ro, vtb + (size_t)r * TLEN + c * 8);
        }
        CP_COMMIT(); CP_WAIT(0);
    }
    __syncthreads();

    // hoist Q fragments (4 k16-chunks), scale by (1/8)*log2(e) in fp32
    const float QSCALE = 0.125f * 1.4426950408889634f;
    uint32_t qf[4][4];
#pragma unroll
    for (int kd = 0; kd < 4; kd++) {
        ldsm_x4(qf[kd], sb + ATILE_B + (uint32_t)(((w * 16) * AST + kd * 16) * 2) + aoff);
#pragma unroll
        for (int e = 0; e < 4; e++)
            qf[kd][e] = scale_h2(qf[kd][e], QSCALE);
    }

    float so[8][4];
    float mrow[2] = {-1e30f, -1e30f}, lsum[2] = {0.f, 0.f};
#pragma unroll
    for (int nt = 0; nt < 8; nt++)
#pragma unroll
        for (int e = 0; e < 4; e++) so[nt][e] = 0.f;

    for (int kt = 0; kt <= qt; kt++) {
        const int p = kt & 1;
        const uint32_t sK = sb + (uint32_t)(p * ATILE_B);
        const uint32_t sV = sb + (uint32_t)((2 + p) * ATILE_B);

        __syncthreads();   // barrier A: prev iter's reads of parity 1-p complete

        if (kt < qt) {
            const uint32_t nK = sb + (uint32_t)((1 - p) * ATILE_B);
            const uint32_t nV = sb + (uint32_t)((2 + (1 - p)) * ATILE_B);
            const int k0r = (kt + 1) * 64;
#pragma unroll
            for (int pp = 0; pp < 4; pp++) {
                const int idx = tid + 128 * pp;
                const int r = idx >> 3, c = idx & 7;
                const uint32_t ro = (uint32_t)(r * (AST * 2) + c * 16);
                CP16(nK + ro, kb + (size_t)(k0r + r) * rs + c * 8);
                CP16(nV + ro, vtb + (size_t)r * TLEN + k0r + c * 8);
            }
            CP_COMMIT();
            CP_WAIT(1);
        } else {
            CP_WAIT(0);
        }
        __syncthreads();    // barrier B: K_p / V_p visible

        // ---- S = Q K^T (fp16 m16n8k16, log2 domain) ----
        float sc[8][4];
#pragma unroll
        for (int nt = 0; nt < 8; nt++)
#pragma unroll
            for (int e = 0; e < 4; e++) sc[nt][e] = 0.f;

#pragma unroll
        for (int kd = 0; kd < 4; kd++) {
            uint32_t bf[4][4];
#pragma unroll
            for (int pr = 0; pr < 4; pr++)
                ldsm_x4(bf[pr], sK + (uint32_t)(((pr * 16) * AST + kd * 16) * 2) + boff);
#pragma unroll
            for (int nt = 0; nt < 8; nt++)
                mma_f16(sc[nt], qf[kd], bf[nt >> 1] + (nt & 1) * 2);
        }

        // ---- causal mask on diagonal tile ----
        if (kt == qt) {
            const int r0 = w * 16 + g, r1 = r0 + 8;
#pragma unroll
            for (int nt = 0; nt < 8; nt++) {
                const int c = nt * 8 + 2 * q;
                if (c     > r0) sc[nt][0] = -1e30f;
                if (c + 1 > r0) sc[nt][1] = -1e30f;
                if (c     > r1) sc[nt][2] = -1e30f;
                if (c + 1 > r1) sc[nt][3] = -1e30f;
            }
        }

        // ---- online softmax (base-2; 2 rows per thread) ----
        float mx0 = -1e30f, mx1 = -1e30f;
#pragma unroll
        for (int nt = 0; nt < 8; nt++) {
            mx0 = fmaxf(mx0, fmaxf(sc[nt][0], sc[nt][1]));
            mx1 = fmaxf(mx1, fmaxf(sc[nt][2], sc[nt][3]));
        }
        mx0 = fmaxf(mx0, __shfl_xor_sync(0xffffffffu, mx0, 1));
        mx0 = fmaxf(mx0, __shfl_xor_sync(0xffffffffu, mx0, 2));
        mx1 = fmaxf(mx1, __shfl_xor_sync(0xffffffffu, mx1, 1));
        mx1 = fmaxf(mx1, __shfl_xor_sync(0xffffffffu, mx1, 2));

        const float mn0 = fmaxf(mrow[0], mx0);
        const float mn1 = fmaxf(mrow[1], mx1);
        const float al0 = ex2f(mrow[0] - mn0);
        const float al1 = ex2f(mrow[1] - mn1);
        mrow[0] = mn0; mrow[1] = mn1;

        float s0 = 0.f, s1 = 0.f;
#pragma unroll
        for (int nt = 0; nt < 8; nt++) {
            sc[nt][0] = ex2f(sc[nt][0] - mn0); s0 += sc[nt][0];
            sc[nt][1] = ex2f(sc[nt][1] - mn0); s0 += sc[nt][1];
            sc[nt][2] = ex2f(sc[nt][2] - mn1); s1 += sc[nt][2];
            sc[nt][3] = ex2f(sc[nt][3] - mn1); s1 += sc[nt][3];
        }
        s0 += __shfl_xor_sync(0xffffffffu, s0, 1);
        s0 += __shfl_xor_sync(0xffffffffu, s0, 2);
        s1 += __shfl_xor_sync(0xffffffffu, s1, 1);
        s1 += __shfl_xor_sync(0xffffffffu, s1, 2);
        lsum[0] = lsum[0] * al0 + s0;
        lsum[1] = lsum[1] * al1 + s1;

#pragma unroll
        for (int nt = 0; nt < 8; nt++) {
            so[nt][0] *= al0; so[nt][1] *= al0;
            so[nt][2] *= al1; so[nt][3] *= al1;
        }

        // ---- pack P to fp16 a-frags in registers (no smem round-trip) ----
        uint32_t pa[4][4];
#pragma unroll
        for (int kc = 0; kc < 4; kc++) {
            pa[kc][0] = pack_f16(sc[2 * kc][0],     sc[2 * kc][1]);
            pa[kc][1] = pack_f16(sc[2 * kc][2],     sc[2 * kc][3]);
            pa[kc][2] = pack_f16(sc[2 * kc + 1][0], sc[2 * kc + 1][1]);
            pa[kc][3] = pack_f16(sc[2 * kc + 1][2], sc[2 * kc + 1][3]);
        }

        // ---- O += P V  (fp16 mma; b-frags = plain LDS.32 from Vt[d][key]) ----
        const char* vbase = (const char*)sma + (2 + p) * ATILE_B;
#pragma unroll
        for (int kc = 0; kc < 4; kc++) {
#pragma unroll
            for (int nt = 0; nt < 8; nt++) {
                const int row = nt * 8 + g;
                const char* vp = vbase + row * (AST * 2) + kc * 32 + q * 4;
                uint32_t bf[2];
                bf[0] = *(const uint32_t*)(vp);
                bf[1] = *(const uint32_t*)(vp + 16);
                mma_f16(so[nt], pa[kc], bf);
            }
        }
    }

    // ---- normalize + store y as fp16 (for fp16 GEMM2) ----
    {
        const float inv0 = 1.f / lsum[0];
        const float inv1 = 1.f / lsum[1];
        const int r0 = q0 + w * 16 + g;
        __half* yb = g_yh + (size_t)b * TLEN * CDIM + h * DH;
#pragma unroll
        for (int nt = 0; nt < 8; nt++) {
            const int c = nt * 8 + 2 * q;
            *(uint32_t*)(yb + (size_t)r0 * CDIM + c) =
                pack_f16(so[nt][0] * inv0, so[nt][1] * inv0);
            *(uint32_t*)(yb + (size_t)(r0 + 8) * CDIM + c) =
                pack_f16(so[nt][2] * inv1, so[nt][3] * inv1);
        }
    }
}

// ---------------------------------------------------------------------------
extern "C" void kernel_launch(void* const* d_in, const int* in_sizes, int n_in,
                              void* d_out, int out_size)
{
    const float* x      = (const float*)d_in[0];
    const float* W_attn = (const float*)d_in[1];
    const float* b_attn = (const float*)d_in[2];
    const float* W_proj = (const float*)d_in[3];
    const float* b_proj = (const float*)d_in[4];
    float* out = (float*)d_out;

    cudaFuncSetAttribute(gemm_h_kernel, cudaFuncAttributeMaxDynamicSharedMemorySize, HGSMEM);
    cudaFuncSetAttribute(attn_h_kernel, cudaFuncAttributeMaxDynamicSharedMemorySize, ASMEM);

    // 0) pre-convert x; transpose+convert weights (fp16)
    cvt_kernel<<<(MROWS * CDIM) / (256 * 4), 256>>>(x);
    {
        dim3 tb(32, 8);
        transpose_kernel<<<dim3((3 * CDIM) / 32, CDIM / 32), tb>>>(W_attn, CDIM, 3 * CDIM, 0);
        transpose_kernel<<<dim3(CDIM / 32, CDIM / 32), tb>>>(W_proj, CDIM, CDIM, 1);
    }
    // 1) qkv = x @ W_attn + b_attn (fp16 in/out, fp32 accum)
    {
        dim3 grid((3 * CDIM) / 128, MROWS / 128);
        gemm_h_kernel<<<grid, 128, HGSMEM>>>(b_attn, nullptr, MROWS, 3 * CDIM, CDIM, 0);
    }
    // 1b) transpose V slice: g_qkvh -> g_vt[b,h,d,t]
    {
        dim3 tb(32, 8);
        vtrans_kernel<<<dim3(TLEN / 32, 2 * HN, BSZ), tb>>>();
    }
    // 2) flash attention (fp16 QK + fp16 PV) -> g_yh
    {
        dim3 grid(TLEN / 64, HN, BSZ);
        attn_h_kernel<<<grid, 128, ASMEM>>>();
    }
    // 3) out = y @ W_proj + b_proj (fp16 in, fp32 accum + store)
    {
        dim3 grid(CDIM / 128, MROWS / 128);
        gemm_h_kernel<<<grid, 128, HGSMEM>>>(b_proj, out, MROWS, CDIM, CDIM, 1);
    }
}

// round 15
// speedup vs baseline: 1.9041x; 1.0657x over previous
#include <cuda_runtime.h>
#include <cuda_fp16.h>
#include <math.h>
#include <stdint.h>

// Problem constants
#define BSZ 2
#define TLEN 2048
#define CDIM 1024
#define HN 16
#define DH 64
#define MROWS (BSZ * TLEN)   // 4096

// Scratch (allocation-free rule: __device__ globals)
__device__ __half g_qkvh[(size_t)MROWS * 3 * CDIM];   // fp16 qkv [B,T,3C]
__device__ __half g_yh[(size_t)MROWS * CDIM];         // fp16 attention output
__device__ __half g_xh[(size_t)MROWS * CDIM];         // fp16(x)
__device__ __half g_wth[(size_t)4 * CDIM * CDIM];     // fp16(W_attn^T), fp16(W_proj^T)
__device__ __half g_vt[(size_t)BSZ * HN * DH * TLEN]; // V transposed fp16: [b,h,d,t]

// ---------------------------------------------------------------------------
// helpers
// ---------------------------------------------------------------------------
__device__ __forceinline__ void mma_f16(float* d, const uint32_t* a, const uint32_t* b) {
    asm volatile(
        "mma.sync.aligned.m16n8k16.row.col.f32.f16.f16.f32 "
        "{%0,%1,%2,%3}, {%4,%5,%6,%7}, {%8,%9}, {%0,%1,%2,%3};"
        : "+f"(d[0]), "+f"(d[1]), "+f"(d[2]), "+f"(d[3])
        : "r"(a[0]), "r"(a[1]), "r"(a[2]), "r"(a[3]), "r"(b[0]), "r"(b[1]));
}

// pack two fp32 -> fp16x2 reg (lo = low half)
__device__ __forceinline__ uint32_t pack_f16(float lo, float hi) {
    uint32_t r;
    asm("cvt.rn.f16x2.f32 %0, %1, %2;" : "=r"(r) : "f"(hi), "f"(lo));
    return r;
}

// scale a fp16x2 reg by fp32 s (unpack -> fp32 mul -> repack; unbiased)
__device__ __forceinline__ uint32_t scale_h2(uint32_t v, float s) {
    __half2 h = *(__half2*)&v;
    float lo = __low2float(h) * s;
    float hi = __high2float(h) * s;
    return pack_f16(lo, hi);
}

__device__ __forceinline__ float ex2f(float x) {
    float r;
    asm("ex2.approx.f32 %0, %1;" : "=f"(r) : "f"(x));
    return r;
}

__device__ __forceinline__ uint32_t smem_u32(const void* p) {
    uint32_t a;
    asm("{ .reg .u64 t; cvta.to.shared.u64 t, %1; cvt.u32.u64 %0, t; }"
        : "=r"(a) : "l"(p));
    return a;
}

__device__ __forceinline__ void ldsm_x4(uint32_t* r, uint32_t addr) {
    asm volatile("ldmatrix.sync.aligned.m8n8.x4.shared.b16 {%0,%1,%2,%3}, [%4];"
                 : "=r"(r[0]), "=r"(r[1]), "=r"(r[2]), "=r"(r[3]) : "r"(addr));
}

// fp16 (2-byte) fragment offsets, stride in halves.
// a mats: (mlo,klo),(mhi,klo),(mlo,khi),(mhi,khi); b mats: (nlo,klo),(nlo,khi),(nhi,klo),(nhi,khi)
__device__ __forceinline__ uint32_t a_frag_off16(int lane, int stride) {
    int mat = lane >> 3, rw = lane & 7;
    return (uint32_t)(((8 * (mat & 1) + rw) * stride + 8 * (mat >> 1)) * 2);
}
__device__ __forceinline__ uint32_t b_frag_off16(int lane, int stride) {
    int mat = lane >> 3, rw = lane & 7;
    return (uint32_t)(((8 * (mat >> 1) + rw) * stride + 8 * (mat & 1)) * 2);
}

#define CP16(s, g) \
    asm volatile("cp.async.cg.shared.global [%0], [%1], 16;" :: "r"(s), "l"(g) : "memory")
#define CP_COMMIT() asm volatile("cp.async.commit_group;" ::: "memory")
#define CP_WAIT(n)  asm volatile("cp.async.wait_group %0;" :: "n"(n) : "memory")

// ---------------------------------------------------------------------------
// x -> fp16 conversion
// ---------------------------------------------------------------------------
__global__ __launch_bounds__(256) void cvt_kernel(const float* __restrict__ x)
{
    size_t i = ((size_t)blockIdx.x * 256 + threadIdx.x) * 4;
    float4 v = *(const float4*)(x + i);
    uint2 o;
    o.x = pack_f16(v.x, v.y);
    o.y = pack_f16(v.z, v.w);
    *(uint2*)(g_xh + i) = o;
}

// ---------------------------------------------------------------------------
// Weight transpose + fp16: src[K][N] -> g_wth(+off)[N][K]
// ---------------------------------------------------------------------------
__global__ __launch_bounds__(256) void transpose_kernel(
    const float* __restrict__ src, int K, int N, int sel)
{
    __shared__ float t[32][33];
    __half* dst = g_wth + (sel ? (size_t)3 * CDIM * CDIM : 0);
    const int nb = blockIdx.x * 32, kb = blockIdx.y * 32;
    const int x = threadIdx.x, y = threadIdx.y;
#pragma unroll
    for (int j = 0; j < 32; j += 8)
        t[y + j][x] = src[(size_t)(kb + y + j) * N + nb + x];
    __syncthreads();
#pragma unroll
    for (int j = 0; j < 32; j += 8)
        dst[(size_t)(nb + y + j) * K + kb + x] = __float2half(t[x][y + j]);
}

// ---------------------------------------------------------------------------
// V transpose: g_qkvh V slice [b,t,(h,d)] fp16 -> g_vt[b,h,d,t] fp16
// ---------------------------------------------------------------------------
__global__ __launch_bounds__(256) void vtrans_kernel()
{
    __shared__ __half t[32][36];
    const int b = blockIdx.z;
    const int h = blockIdx.y >> 1;
    const int d0 = (blockIdx.y & 1) * 32;
    const int t0 = blockIdx.x * 32;
    const int x = threadIdx.x, y = threadIdx.y;

    const __half* src = g_qkvh + (size_t)b * TLEN * 3 * CDIM + 2 * CDIM + h * DH;
#pragma unroll
    for (int j = 0; j < 32; j += 8)
        t[y + j][x] = src[(size_t)(t0 + y + j) * 3 * CDIM + d0 + x];
    __syncthreads();
    __half* dst = g_vt + ((size_t)(b * HN + h) * DH + d0) * TLEN + t0;
#pragma unroll
    for (int j = 0; j < 32; j += 8)
        dst[(size_t)(y + j) * TLEN + x] = t[x][y + j];
}

// ---------------------------------------------------------------------------
// fp16 GEMM (m16n8k16), BK=64: C[M,N] = A[M,K] @ W[K,N] + bias[N].
// 128x128 tile, 128 threads = 4 warps (2m x 2n), warp tile 64x64,
// 2-stage cp.async ring (73,728 B), 3 CTAs/SM. 16 K-chunks -> half the
// barrier crossings of BK=32; 4x unrolled kk windows for LDSM/HMMA overlap.
// mode 0: A=g_xh, C=g_qkvh (fp16); mode 1: A=g_yh, C=C_param (fp32).
// ---------------------------------------------------------------------------
#define SH 72                        // smem stride (halves); 144B rows, LDSM conflict-free
#define HTILE_B (128 * SH * 2)       // 18432 per tile (A or B)
#define HSTAGE (2 * HTILE_B)         // 36864 per stage
#define HGSMEM (2 * HSTAGE)          // 73728

__global__ __launch_bounds__(128, 3) void gemm_h_kernel(
    const float* __restrict__ bias, float* __restrict__ C_param,
    int M, int N, int K, int mode)
{
    extern __shared__ char smh[];
    const __half* A  = mode ? g_yh : g_xh;
    const __half* Bt = g_wth + (mode ? (size_t)3 * CDIM * CDIM : 0);

    const int tid = threadIdx.x, lane = tid & 31, wid = tid >> 5;
    const int wm = wid >> 1, wn = wid & 1;
    const int g = lane >> 2, q = lane & 3;
    const int m0 = blockIdx.y * 128, n0 = blockIdx.x * 128;
    const uint32_t sb = smem_u32(smh);

    const uint32_t a_off = a_frag_off16(lane, SH);
    const uint32_t b_off = b_frag_off16(lane, SH);

    float acc[4][8][4];
#pragma unroll
    for (int mt = 0; mt < 4; mt++)
#pragma unroll
        for (int nt = 0; nt < 8; nt++)
#pragma unroll
            for (int e = 0; e < 4; e++) acc[mt][nt][e] = 0.f;

    const int nc = K / 64;

    // prefetch stages 0 and 1 (per stage: 128 rows x 8 chunks(16B) per operand)
#pragma unroll
    for (int s = 0; s < 2; s++) {
        const int k0 = s * 64;
        const uint32_t st = sb + (uint32_t)(s * HSTAGE);
#pragma unroll
        for (int i = 0; i < 8; i++) {
            const int f = tid + 128 * i;          // 0..1023
            const int row = f >> 3, c8 = f & 7;
            const uint32_t so = st + (uint32_t)(row * (SH * 2) + c8 * 16);
            CP16(so, A + (size_t)(m0 + row) * K + k0 + c8 * 8);
            CP16(so + HTILE_B, Bt + (size_t)(n0 + row) * K + k0 + c8 * 8);
        }
        CP_COMMIT();
    }

    for (int c = 0; c < nc; c++) {
        if (c == nc - 1) { CP_WAIT(0); } else { CP_WAIT(1); }
        __syncthreads();

        const uint32_t ab = sb + (uint32_t)((c & 1) * HSTAGE);
        const uint32_t bbse = ab + HTILE_B;
#pragma unroll
        for (int kk = 0; kk < 64; kk += 16) {
            uint32_t af[4][4], bf[4][4];
#pragma unroll
            for (int mt = 0; mt < 4; mt++)
                ldsm_x4(af[mt], ab + (uint32_t)(((wm * 64 + mt * 16) * SH + kk) * 2) + a_off);
#pragma unroll
            for (int pr = 0; pr < 4; pr++)
                ldsm_x4(bf[pr], bbse + (uint32_t)(((wn * 64 + pr * 16) * SH + kk) * 2) + b_off);
#pragma unroll
            for (int mt = 0; mt < 4; mt++)
#pragma unroll
                for (int nt = 0; nt < 8; nt++)
                    mma_f16(acc[mt][nt], af[mt], bf[nt >> 1] + (nt & 1) * 2);
        }
        __syncthreads();

        if (c + 2 < nc) {
            const int k0 = (c + 2) * 64;
            const uint32_t st = sb + (uint32_t)((c & 1) * HSTAGE);
#pragma unroll
            for (int i = 0; i < 8; i++) {
                const int f = tid + 128 * i;
                const int row = f >> 3, c8 = f & 7;
                const uint32_t so = st + (uint32_t)(row * (SH * 2) + c8 * 16);
                CP16(so, A + (size_t)(m0 + row) * K + k0 + c8 * 8);
                CP16(so + HTILE_B, Bt + (size_t)(n0 + row) * K + k0 + c8 * 8);
            }
            CP_COMMIT();
        }
    }

    // epilogue: bias (fp32), then fp16 store (mode 0 -> g_qkvh) or fp32 (mode 1)
#pragma unroll
    for (int mt = 0; mt < 4; mt++) {
        int r0 = m0 + wm * 64 + mt * 16 + g;
#pragma unroll
        for (int nt = 0; nt < 8; nt++) {
            int cc = n0 + wn * 64 + nt * 8 + 2 * q;
            float b0 = bias[cc], b1 = bias[cc + 1];
            float v00 = acc[mt][nt][0] + b0, v01 = acc[mt][nt][1] + b1;
            float v10 = acc[mt][nt][2] + b0, v11 = acc[mt][nt][3] + b1;
            if (mode == 0) {
                *(uint32_t*)(g_qkvh + (size_t)r0 * N + cc)       = pack_f16(v00, v01);
                *(uint32_t*)(g_qkvh + (size_t)(r0 + 8) * N + cc) = pack_f16(v10, v11);
            } else {
                *(float2*)(C_param + (size_t)r0 * N + cc)       = make_float2(v00, v01);
                *(float2*)(C_param + (size_t)(r0 + 8) * N + cc) = make_float2(v10, v11);
            }
        }
    }
}

// ---------------------------------------------------------------------------
// Flash attention, all-fp16 MMA (unchanged from R14): fp16 QK^T + fp16 PV
// (FA2 register trick). 64-query tile, 128 threads = 4 warps,
// double-buffered K/V. Smem: K0|K1|V0|V1 = 36,864 B.
// ---------------------------------------------------------------------------
#define AST 72                       // K/V tile stride (halves); 144 B rows, conflict-free
#define ATILE_B (64 * AST * 2)       // 9216
#define ASMEM (4 * ATILE_B)          // 36864

__global__ __launch_bounds__(128, 3) void attn_h_kernel()
{
    extern __shared__ char sma[];

    const int qt = (gridDim.x - 1) - blockIdx.x;   // heavy-first
    const int h = blockIdx.y, b = blockIdx.z;
    const int tid = threadIdx.x, lane = tid & 31, w = tid >> 5;
    const int g = lane >> 2, q = lane & 3;
    const int q0 = qt * 64;

    const uint32_t sb = smem_u32(sma);

    const size_t rs = 3 * CDIM;
    const __half* qb  = g_qkvh + (size_t)b * TLEN * rs + h * DH;
    const __half* kb  = qb + CDIM;
    const __half* vtb = g_vt + (size_t)(b * HN + h) * DH * TLEN;

    const uint32_t aoff = a_frag_off16(lane, AST);
    const uint32_t boff = b_frag_off16(lane, AST);

    // ---- preload: Q -> K1 region; K tile 0 -> K0; Vt tile 0 -> V0 ----
    {
        const uint32_t sQ = sb + ATILE_B;
#pragma unroll
        for (int p = 0; p < 4; p++) {
            const int idx = tid + 128 * p;            // 0..511
            const int r = idx >> 3, c = idx & 7;
            const uint32_t ro = (uint32_t)(r * (AST * 2) + c * 16);
            CP16(sQ + ro, qb + (size_t)(q0 + r) * rs + c * 8);
            CP16(sb + ro, kb + (size_t)r * rs + c * 8);
            CP16(sb + 2 * ATILE_B + ro, vtb + (size_t)r * TLEN + c * 8);
        }
        CP_COMMIT(); CP_WAIT(0);
    }
    __syncthreads();

    // hoist Q fragments (4 k16-chunks), scale by (1/8)*log2(e) in fp32
    const float QSCALE = 0.125f * 1.4426950408889634f;
    uint32_t qf[4][4];
#pragma unroll
    for (int kd = 0; kd < 4; kd++) {
        ldsm_x4(qf[kd], sb + ATILE_B + (uint32_t)(((w * 16) * AST + kd * 16) * 2) + aoff);
#pragma unroll
        for (int e = 0; e < 4; e++)
            qf[kd][e] = scale_h2(qf[kd][e], QSCALE);
    }

    float so[8][4];
    float mrow[2] = {-1e30f, -1e30f}, lsum[2] = {0.f, 0.f};
#pragma unroll
    for (int nt = 0; nt < 8; nt++)
#pragma unroll
        for (int e = 0; e < 4; e++) so[nt][e] = 0.f;

    for (int kt = 0; kt <= qt; kt++) {
        const int p = kt & 1;
        const uint32_t sK = sb + (uint32_t)(p * ATILE_B);

        __syncthreads();   // barrier A: prev iter's reads of parity 1-p complete

        if (kt < qt) {
            const uint32_t nK = sb + (uint32_t)((1 - p) * ATILE_B);
            const uint32_t nV = sb + (uint32_t)((2 + (1 - p)) * ATILE_B);
            const int k0r = (kt + 1) * 64;
#pragma unroll
            for (int pp = 0; pp < 4; pp++) {
                const int idx = tid + 128 * pp;
                const int r = idx >> 3, c = idx & 7;
                const uint32_t ro = (uint32_t)(r * (AST * 2) + c * 16);
                CP16(nK + ro, kb + (size_t)(k0r + r) * rs + c * 8);
                CP16(nV + ro, vtb + (size_t)r * TLEN + k0r + c * 8);
            }
            CP_COMMIT();
            CP_WAIT(1);
        } else {
            CP_WAIT(0);
        }
        __syncthreads();    // barrier B: K_p / V_p visible

        // ---- S = Q K^T (fp16 m16n8k16, log2 domain) ----
        float sc[8][4];
#pragma unroll
        for (int nt = 0; nt < 8; nt++)
#pragma unroll
            for (int e = 0; e < 4; e++) sc[nt][e] = 0.f;

#pragma unroll
        for (int kd = 0; kd < 4; kd++) {
            uint32_t bf[4][4];
#pragma unroll
            for (int pr = 0; pr < 4; pr++)
                ldsm_x4(bf[pr], sK + (uint32_t)(((pr * 16) * AST + kd * 16) * 2) + boff);
#pragma unroll
            for (int nt = 0; nt < 8; nt++)
                mma_f16(sc[nt], qf[kd], bf[nt >> 1] + (nt & 1) * 2);
        }

        // ---- causal mask on diagonal tile ----
        if (kt == qt) {
            const int r0 = w * 16 + g, r1 = r0 + 8;
#pragma unroll
            for (int nt = 0; nt < 8; nt++) {
                const int c = nt * 8 + 2 * q;
                if (c     > r0) sc[nt][0] = -1e30f;
                if (c + 1 > r0) sc[nt][1] = -1e30f;
                if (c     > r1) sc[nt][2] = -1e30f;
                if (c + 1 > r1) sc[nt][3] = -1e30f;
            }
        }

        // ---- online softmax (base-2; 2 rows per thread) ----
        float mx0 = -1e30f, mx1 = -1e30f;
#pragma unroll
        for (int nt = 0; nt < 8; nt++) {
            mx0 = fmaxf(mx0, fmaxf(sc[nt][0], sc[nt][1]));
            mx1 = fmaxf(mx1, fmaxf(sc[nt][2], sc[nt][3]));
        }
        mx0 = fmaxf(mx0, __shfl_xor_sync(0xffffffffu, mx0, 1));
        mx0 = fmaxf(mx0, __shfl_xor_sync(0xffffffffu, mx0, 2));
        mx1 = fmaxf(mx1, __shfl_xor_sync(0xffffffffu, mx1, 1));
        mx1 = fmaxf(mx1, __shfl_xor_sync(0xffffffffu, mx1, 2));

        const float mn0 = fmaxf(mrow[0], mx0);
        const float mn1 = fmaxf(mrow[1], mx1);
        const float al0 = ex2f(mrow[0] - mn0);
        const float al1 = ex2f(mrow[1] - mn1);
        mrow[0] = mn0; mrow[1] = mn1;

        float s0 = 0.f, s1 = 0.f;
#pragma unroll
        for (int nt = 0; nt < 8; nt++) {
            sc[nt][0] = ex2f(sc[nt][0] - mn0); s0 += sc[nt][0];
            sc[nt][1] = ex2f(sc[nt][1] - mn0); s0 += sc[nt][1];
            sc[nt][2] = ex2f(sc[nt][2] - mn1); s1 += sc[nt][2];
            sc[nt][3] = ex2f(sc[nt][3] - mn1); s1 += sc[nt][3];
        }
        s0 += __shfl_xor_sync(0xffffffffu, s0, 1);
        s0 += __shfl_xor_sync(0xffffffffu, s0, 2);
        s1 += __shfl_xor_sync(0xffffffffu, s1, 1);
        s1 += __shfl_xor_sync(0xffffffffu, s1, 2);
        lsum[0] = lsum[0] * al0 + s0;
        lsum[1] = lsum[1] * al1 + s1;

#pragma unroll
        for (int nt = 0; nt < 8; nt++) {
            so[nt][0] *= al0; so[nt][1] *= al0;
            so[nt][2] *= al1; so[nt][3] *= al1;
        }

        // ---- pack P to fp16 a-frags in registers (no smem round-trip) ----
        uint32_t pa[4][4];
#pragma unroll
        for (int kc = 0; kc < 4; kc++) {
            pa[kc][0] = pack_f16(sc[2 * kc][0],     sc[2 * kc][1]);
            pa[kc][1] = pack_f16(sc[2 * kc][2],     sc[2 * kc][3]);
            pa[kc][2] = pack_f16(sc[2 * kc + 1][0], sc[2 * kc + 1][1]);
            pa[kc][3] = pack_f16(sc[2 * kc + 1][2], sc[2 * kc + 1][3]);
        }

        // ---- O += P V  (fp16 mma; b-frags = plain LDS.32 from Vt[d][key]) ----
        const char* vbase = (const char*)sma + (2 + p) * ATILE_B;
#pragma unroll
        for (int kc = 0; kc < 4; kc++) {
#pragma unroll
            for (int nt = 0; nt < 8; nt++) {
                const int row = nt * 8 + g;
                const char* vp = vbase + row * (AST * 2) + kc * 32 + q * 4;
                uint32_t bf[2];
                bf[0] = *(const uint32_t*)(vp);
                bf[1] = *(const uint32_t*)(vp + 16);
                mma_f16(so[nt], pa[kc], bf);
            }
        }
    }

    // ---- normalize + store y as fp16 (for fp16 GEMM2) ----
    {
        const float inv0 = 1.f / lsum[0];
        const float inv1 = 1.f / lsum[1];
        const int r0 = q0 + w * 16 + g;
        __half* yb = g_yh + (size_t)b * TLEN * CDIM + h * DH;
#pragma unroll
        for (int nt = 0; nt < 8; nt++) {
            const int c = nt * 8 + 2 * q;
            *(uint32_t*)(yb + (size_t)r0 * CDIM + c) =
                pack_f16(so[nt][0] * inv0, so[nt][1] * inv0);
            *(uint32_t*)(yb + (size_t)(r0 + 8) * CDIM + c) =
                pack_f16(so[nt][2] * inv1, so[nt][3] * inv1);
        }
    }
}

// ---------------------------------------------------------------------------
extern "C" void kernel_launch(void* const* d_in, const int* in_sizes, int n_in,
                              void* d_out, int out_size)
{
    const float* x      = (const float*)d_in[0];
    const float* W_attn = (const float*)d_in[1];
    const float* b_attn = (const float*)d_in[2];
    const float* W_proj = (const float*)d_in[3];
    const float* b_proj = (const float*)d_in[4];
    float* out = (float*)d_out;

    cudaFuncSetAttribute(gemm_h_kernel, cudaFuncAttributeMaxDynamicSharedMemorySize, HGSMEM);
    cudaFuncSetAttribute(attn_h_kernel, cudaFuncAttributeMaxDynamicSharedMemorySize, ASMEM);

    // 0) pre-convert x; transpose+convert weights (fp16)
    cvt_kernel<<<(MROWS * CDIM) / (256 * 4), 256>>>(x);
    {
        dim3 tb(32, 8);
        transpose_kernel<<<dim3((3 * CDIM) / 32, CDIM / 32), tb>>>(W_attn, CDIM, 3 * CDIM, 0);
        transpose_kernel<<<dim3(CDIM / 32, CDIM / 32), tb>>>(W_proj, CDIM, CDIM, 1);
    }
    // 1) qkv = x @ W_attn + b_attn (fp16 in/out, fp32 accum)
    {
        dim3 grid((3 * CDIM) / 128, MROWS / 128);
        gemm_h_kernel<<<grid, 128, HGSMEM>>>(b_attn, nullptr, MROWS, 3 * CDIM, CDIM, 0);
    }
    // 1b) transpose V slice: g_qkvh -> g_vt[b,h,d,t]
    {
        dim3 tb(32, 8);
        vtrans_kernel<<<dim3(TLEN / 32, 2 * HN, BSZ), tb>>>();
    }
    // 2) flash attention (fp16 QK + fp16 PV) -> g_yh
    {
        dim3 grid(TLEN / 64, HN, BSZ);
        attn_h_kernel<<<grid, 128, ASMEM>>>();
    }
    // 3) out = y @ W_proj + b_proj (fp16 in, fp32 accum + store)
    {
        dim3 grid(CDIM / 128, MROWS / 128);
        gemm_h_kernel<<<grid, 128, HGSMEM>>>(b_proj, out, MROWS, CDIM, CDIM, 1);
    }
}

// round 16
// speedup vs baseline: 1.9808x; 1.0403x over previous
#include <cuda_runtime.h>
#include <cuda_fp16.h>
#include <math.h>
#include <stdint.h>

// Problem constants
#define BSZ 2
#define TLEN 2048
#define CDIM 1024
#define HN 16
#define DH 64
#define MROWS (BSZ * TLEN)   // 4096

// Scratch (allocation-free rule: __device__ globals)
__device__ __half g_qkvh[(size_t)MROWS * 3 * CDIM];   // fp16 qkv [B,T,3C]
__device__ __half g_yh[(size_t)MROWS * CDIM];         // fp16 attention output
__device__ __half g_xh[(size_t)MROWS * CDIM];         // fp16(x)
__device__ __half g_wth[(size_t)4 * CDIM * CDIM];     // fp16(W_attn^T), fp16(W_proj^T)

// ---------------------------------------------------------------------------
// helpers
// ---------------------------------------------------------------------------
__device__ __forceinline__ void mma_f16(float* d, const uint32_t* a, const uint32_t* b) {
    asm volatile(
        "mma.sync.aligned.m16n8k16.row.col.f32.f16.f16.f32 "
        "{%0,%1,%2,%3}, {%4,%5,%6,%7}, {%8,%9}, {%0,%1,%2,%3};"
        : "+f"(d[0]), "+f"(d[1]), "+f"(d[2]), "+f"(d[3])
        : "r"(a[0]), "r"(a[1]), "r"(a[2]), "r"(a[3]), "r"(b[0]), "r"(b[1]));
}

// pack two fp32 -> fp16x2 reg (lo = low half)
__device__ __forceinline__ uint32_t pack_f16(float lo, float hi) {
    uint32_t r;
    asm("cvt.rn.f16x2.f32 %0, %1, %2;" : "=r"(r) : "f"(hi), "f"(lo));
    return r;
}

// scale a fp16x2 reg by fp32 s (unpack -> fp32 mul -> repack; unbiased)
__device__ __forceinline__ uint32_t scale_h2(uint32_t v, float s) {
    __half2 h = *(__half2*)&v;
    float lo = __low2float(h) * s;
    float hi = __high2float(h) * s;
    return pack_f16(lo, hi);
}

__device__ __forceinline__ float ex2f(float x) {
    float r;
    asm("ex2.approx.f32 %0, %1;" : "=f"(r) : "f"(x));
    return r;
}

__device__ __forceinline__ uint32_t smem_u32(const void* p) {
    uint32_t a;
    asm("{ .reg .u64 t; cvta.to.shared.u64 t, %1; cvt.u32.u64 %0, t; }"
        : "=r"(a) : "l"(p));
    return a;
}

__device__ __forceinline__ void ldsm_x4(uint32_t* r, uint32_t addr) {
    asm volatile("ldmatrix.sync.aligned.m8n8.x4.shared.b16 {%0,%1,%2,%3}, [%4];"
                 : "=r"(r[0]), "=r"(r[1]), "=r"(r[2]), "=r"(r[3]) : "r"(addr));
}

__device__ __forceinline__ void ldsm_x4_trans(uint32_t* r, uint32_t addr) {
    asm volatile("ldmatrix.sync.aligned.m8n8.x4.trans.shared.b16 {%0,%1,%2,%3}, [%4];"
                 : "=r"(r[0]), "=r"(r[1]), "=r"(r[2]), "=r"(r[3]) : "r"(addr));
}

// fp16 (2-byte) fragment offsets, stride in halves.
// a mats: (mlo,klo),(mhi,klo),(mlo,khi),(mhi,khi); b mats: (nlo,klo),(nlo,khi),(nhi,klo),(nhi,khi)
__device__ __forceinline__ uint32_t a_frag_off16(int lane, int stride) {
    int mat = lane >> 3, rw = lane & 7;
    return (uint32_t)(((8 * (mat & 1) + rw) * stride + 8 * (mat >> 1)) * 2);
}
__device__ __forceinline__ uint32_t b_frag_off16(int lane, int stride) {
    int mat = lane >> 3, rw = lane & 7;
    return (uint32_t)(((8 * (mat >> 1) + rw) * stride + 8 * (mat & 1)) * 2);
}
// trans-V fragment offset for [key][d] tiles: mats (klo,d0),(khi,d0),(klo,d1),(khi,d1)
// -> rows 8*(mat&1)+rw, col halves 8*(mat>>1): same math as a_frag_off16.

#define CP16(s, g) \
    asm volatile("cp.async.cg.shared.global [%0], [%1], 16;" :: "r"(s), "l"(g) : "memory")
#define CP_COMMIT() asm volatile("cp.async.commit_group;" ::: "memory")
#define CP_WAIT(n)  asm volatile("cp.async.wait_group %0;" :: "n"(n) : "memory")

// ---------------------------------------------------------------------------
// x -> fp16 conversion (8 floats / thread, 16B stores)
// ---------------------------------------------------------------------------
__global__ __launch_bounds__(256) void cvt_kernel(const float* __restrict__ x)
{
    size_t i = ((size_t)blockIdx.x * 256 + threadIdx.x) * 8;
    float4 v0 = *(const float4*)(x + i);
    float4 v1 = *(const float4*)(x + i + 4);
    uint4 o;
    o.x = pack_f16(v0.x, v0.y);
    o.y = pack_f16(v0.z, v0.w);
    o.z = pack_f16(v1.x, v1.y);
    o.w = pack_f16(v1.z, v1.w);
    *(uint4*)(g_xh + i) = o;
}

// ---------------------------------------------------------------------------
// Weight transpose + fp16 with coalesced wide stores:
// src[K][N] fp32 -> g_wth(+off)[N][K] fp16.
// Tile: 64 k-rows x 32 n-cols. Block 256.
// Read: 64 rows x 8 float4 (128B rows). Write: 32 rows x 8 uint4 (128B rows).
// ---------------------------------------------------------------------------
__global__ __launch_bounds__(256) void transpose_kernel(
    const float* __restrict__ src, int K, int N, int sel)
{
    __shared__ __half st[32][72];      // [n][k], 144B row stride
    __half* dst = g_wth + (sel ? (size_t)3 * CDIM * CDIM : 0);
    const int nb = blockIdx.x * 32, kb = blockIdx.y * 64;
    const int tid = threadIdx.x;

#pragma unroll
    for (int it = 0; it < 2; it++) {
        const int f = tid + 256 * it;          // 0..511
        const int row = f >> 3;                // k row 0..63
        const int c4 = f & 7;                  // float4 col 0..7
        float4 v = *(const float4*)(src + (size_t)(kb + row) * N + nb + c4 * 4);
        st[c4 * 4 + 0][row] = __float2half(v.x);
        st[c4 * 4 + 1][row] = __float2half(v.y);
        st[c4 * 4 + 2][row] = __float2half(v.z);
        st[c4 * 4 + 3][row] = __float2half(v.w);
    }
    __syncthreads();

    {
        const int n = tid >> 3;                // 0..31
        const int ch = tid & 7;                // 16B chunk 0..7
        uint4 v = *(const uint4*)&st[n][ch * 8];
        *(uint4*)(dst + (size_t)(nb + n) * K + kb + ch * 8) = v;
    }
}

// ---------------------------------------------------------------------------
// fp16 GEMM (m16n8k16), BK=64 (unchanged from R15): 128x128 tile,
// 128 threads = 4 warps (2m x 2n), warp tile 64x64, 2-stage ring, 3 CTAs/SM.
// mode 0: A=g_xh, C=g_qkvh (fp16); mode 1: A=g_yh, C=C_param (fp32).
// ---------------------------------------------------------------------------
#define SH 72                        // smem stride (halves); 144B rows, LDSM conflict-free
#define HTILE_B (128 * SH * 2)       // 18432 per tile (A or B)
#define HSTAGE (2 * HTILE_B)         // 36864 per stage
#define HGSMEM (2 * HSTAGE)          // 73728

__global__ __launch_bounds__(128, 3) void gemm_h_kernel(
    const float* __restrict__ bias, float* __restrict__ C_param,
    int M, int N, int K, int mode)
{
    extern __shared__ char smh[];
    const __half* A  = mode ? g_yh : g_xh;
    const __half* Bt = g_wth + (mode ? (size_t)3 * CDIM * CDIM : 0);

    const int tid = threadIdx.x, lane = tid & 31, wid = tid >> 5;
    const int wm = wid >> 1, wn = wid & 1;
    const int g = lane >> 2, q = lane & 3;
    const int m0 = blockIdx.y * 128, n0 = blockIdx.x * 128;
    const uint32_t sb = smem_u32(smh);

    const uint32_t a_off = a_frag_off16(lane, SH);
    const uint32_t b_off = b_frag_off16(lane, SH);

    float acc[4][8][4];
#pragma unroll
    for (int mt = 0; mt < 4; mt++)
#pragma unroll
        for (int nt = 0; nt < 8; nt++)
#pragma unroll
            for (int e = 0; e < 4; e++) acc[mt][nt][e] = 0.f;

    const int nc = K / 64;

#pragma unroll
    for (int s = 0; s < 2; s++) {
        const int k0 = s * 64;
        const uint32_t st = sb + (uint32_t)(s * HSTAGE);
#pragma unroll
        for (int i = 0; i < 8; i++) {
            const int f = tid + 128 * i;
            const int row = f >> 3, c8 = f & 7;
            const uint32_t so = st + (uint32_t)(row * (SH * 2) + c8 * 16);
            CP16(so, A + (size_t)(m0 + row) * K + k0 + c8 * 8);
            CP16(so + HTILE_B, Bt + (size_t)(n0 + row) * K + k0 + c8 * 8);
        }
        CP_COMMIT();
    }

    for (int c = 0; c < nc; c++) {
        if (c == nc - 1) { CP_WAIT(0); } else { CP_WAIT(1); }
        __syncthreads();

        const uint32_t ab = sb + (uint32_t)((c & 1) * HSTAGE);
        const uint32_t bbse = ab + HTILE_B;
#pragma unroll
        for (int kk = 0; kk < 64; kk += 16) {
            uint32_t af[4][4], bf[4][4];
#pragma unroll
            for (int mt = 0; mt < 4; mt++)
                ldsm_x4(af[mt], ab + (uint32_t)(((wm * 64 + mt * 16) * SH + kk) * 2) + a_off);
#pragma unroll
            for (int pr = 0; pr < 4; pr++)
                ldsm_x4(bf[pr], bbse + (uint32_t)(((wn * 64 + pr * 16) * SH + kk) * 2) + b_off);
#pragma unroll
            for (int mt = 0; mt < 4; mt++)
#pragma unroll
                for (int nt = 0; nt < 8; nt++)
                    mma_f16(acc[mt][nt], af[mt], bf[nt >> 1] + (nt & 1) * 2);
        }
        __syncthreads();

        if (c + 2 < nc) {
            const int k0 = (c + 2) * 64;
            const uint32_t st = sb + (uint32_t)((c & 1) * HSTAGE);
#pragma unroll
            for (int i = 0; i < 8; i++) {
                const int f = tid + 128 * i;
                const int row = f >> 3, c8 = f & 7;
                const uint32_t so = st + (uint32_t)(row * (SH * 2) + c8 * 16);
                CP16(so, A + (size_t)(m0 + row) * K + k0 + c8 * 8);
                CP16(so + HTILE_B, Bt + (size_t)(n0 + row) * K + k0 + c8 * 8);
            }
            CP_COMMIT();
        }
    }

    // epilogue: bias (fp32), then fp16 store (mode 0 -> g_qkvh) or fp32 (mode 1)
#pragma unroll
    for (int mt = 0; mt < 4; mt++) {
        int r0 = m0 + wm * 64 + mt * 16 + g;
#pragma unroll
        for (int nt = 0; nt < 8; nt++) {
            int cc = n0 + wn * 64 + nt * 8 + 2 * q;
            float b0 = bias[cc], b1 = bias[cc + 1];
            float v00 = acc[mt][nt][0] + b0, v01 = acc[mt][nt][1] + b1;
            float v10 = acc[mt][nt][2] + b0, v11 = acc[mt][nt][3] + b1;
            if (mode == 0) {
                *(uint32_t*)(g_qkvh + (size_t)r0 * N + cc)       = pack_f16(v00, v01);
                *(uint32_t*)(g_qkvh + (size_t)(r0 + 8) * N + cc) = pack_f16(v10, v11);
            } else {
                *(float2*)(C_param + (size_t)r0 * N + cc)       = make_float2(v00, v01);
                *(float2*)(C_param + (size_t)(r0 + 8) * N + cc) = make_float2(v10, v11);
            }
        }
    }
}

// ---------------------------------------------------------------------------
// Flash attention, all-fp16 MMA: fp16 QK^T + fp16 PV. V loaded in K-layout
// [key][d] straight from g_qkvh; PV b-frags produced via ldmatrix.x4.trans
// (no pre-transpose kernel, no g_vt). 64-query tile, 128 threads = 4 warps,
// double-buffered K/V. Smem: K0|K1|V0|V1 = 36,864 B, 3 CTAs/SM.
// ---------------------------------------------------------------------------
#define AST 72                       // K/V tile stride (halves); 144 B rows, conflict-free
#define ATILE_B (64 * AST * 2)       // 9216
#define ASMEM (4 * ATILE_B)          // 36864

__global__ __launch_bounds__(128, 3) void attn_h_kernel()
{
    extern __shared__ char sma[];

    const int qt = (gridDim.x - 1) - blockIdx.x;   // heavy-first
    const int h = blockIdx.y, b = blockIdx.z;
    const int tid = threadIdx.x, lane = tid & 31, w = tid >> 5;
    const int g = lane >> 2, q = lane & 3;
    const int q0 = qt * 64;

    const uint32_t sb = smem_u32(sma);

    const size_t rs = 3 * CDIM;
    const __half* qb = g_qkvh + (size_t)b * TLEN * rs + h * DH;
    const __half* kb = qb + CDIM;
    const __half* vb = qb + 2 * CDIM;

    const uint32_t aoff = a_frag_off16(lane, AST);
    const uint32_t boff = b_frag_off16(lane, AST);
    const uint32_t vtoff = a_frag_off16(lane, AST);   // trans-V frag offset

    // ---- preload: Q -> K1 region; K tile 0 -> K0; V tile 0 -> V0 ----
    {
        const uint32_t sQ = sb + ATILE_B;
#pragma unroll
        for (int p = 0; p < 4; p++) {
            const int idx = tid + 128 * p;            // 0..511
            const int r = idx >> 3, c = idx & 7;
            const uint32_t ro = (uint32_t)(r * (AST * 2) + c * 16);
            CP16(sQ + ro, qb + (size_t)(q0 + r) * rs + c * 8);
            CP16(sb + ro, kb + (size_t)r * rs + c * 8);
            CP16(sb + 2 * ATILE_B + ro, vb + (size_t)r * rs + c * 8);
        }
        CP_COMMIT(); CP_WAIT(0);
    }
    __syncthreads();

    // hoist Q fragments (4 k16-chunks), scale by (1/8)*log2(e) in fp32
    const float QSCALE = 0.125f * 1.4426950408889634f;
    uint32_t qf[4][4];
#pragma unroll
    for (int kd = 0; kd < 4; kd++) {
        ldsm_x4(qf[kd], sb + ATILE_B + (uint32_t)(((w * 16) * AST + kd * 16) * 2) + aoff);
#pragma unroll
        for (int e = 0; e < 4; e++)
            qf[kd][e] = scale_h2(qf[kd][e], QSCALE);
    }

    float so[8][4];
    float mrow[2] = {-1e30f, -1e30f}, lsum[2] = {0.f, 0.f};
#pragma unroll
    for (int nt = 0; nt < 8; nt++)
#pragma unroll
        for (int e = 0; e < 4; e++) so[nt][e] = 0.f;

    for (int kt = 0; kt <= qt; kt++) {
        const int p = kt & 1;
        const uint32_t sK = sb + (uint32_t)(p * ATILE_B);
        const uint32_t sV = sb + (uint32_t)((2 + p) * ATILE_B);

        __syncthreads();   // barrier A: prev iter's reads of parity 1-p complete

        if (kt < qt) {
            const uint32_t nK = sb + (uint32_t)((1 - p) * ATILE_B);
            const uint32_t nV = sb + (uint32_t)((2 + (1 - p)) * ATILE_B);
            const int k0r = (kt + 1) * 64;
#pragma unroll
            for (int pp = 0; pp < 4; pp++) {
                const int idx = tid + 128 * pp;
                const int r = idx >> 3, c = idx & 7;
                const uint32_t ro = (uint32_t)(r * (AST * 2) + c * 16);
                CP16(nK + ro, kb + (size_t)(k0r + r) * rs + c * 8);
                CP16(nV + ro, vb + (size_t)(k0r + r) * rs + c * 8);
            }
            CP_COMMIT();
            CP_WAIT(1);
        } else {
            CP_WAIT(0);
        }
        __syncthreads();    // barrier B: K_p / V_p visible

        // ---- S = Q K^T (fp16 m16n8k16, log2 domain) ----
        float sc[8][4];
#pragma unroll
        for (int nt = 0; nt < 8; nt++)
#pragma unroll
            for (int e = 0; e < 4; e++) sc[nt][e] = 0.f;

#pragma unroll
        for (int kd = 0; kd < 4; kd++) {
            uint32_t bf[4][4];
#pragma unroll
            for (int pr = 0; pr < 4; pr++)
                ldsm_x4(bf[pr], sK + (uint32_t)(((pr * 16) * AST + kd * 16) * 2) + boff);
#pragma unroll
            for (int nt = 0; nt < 8; nt++)
                mma_f16(sc[nt], qf[kd], bf[nt >> 1] + (nt & 1) * 2);
        }

        // ---- causal mask on diagonal tile ----
        if (kt == qt) {
            const int r0 = w * 16 + g, r1 = r0 + 8;
#pragma unroll
            for (int nt = 0; nt < 8; nt++) {
                const int c = nt * 8 + 2 * q;
                if (c     > r0) sc[nt][0] = -1e30f;
                if (c + 1 > r0) sc[nt][1] = -1e30f;
                if (c     > r1) sc[nt][2] = -1e30f;
                if (c + 1 > r1) sc[nt][3] = -1e30f;
            }
        }

        // ---- online softmax (base-2; 2 rows per thread) ----
        float mx0 = -1e30f, mx1 = -1e30f;
#pragma unroll
        for (int nt = 0; nt < 8; nt++) {
            mx0 = fmaxf(mx0, fmaxf(sc[nt][0], sc[nt][1]));
            mx1 = fmaxf(mx1, fmaxf(sc[nt][2], sc[nt][3]));
        }
        mx0 = fmaxf(mx0, __shfl_xor_sync(0xffffffffu, mx0, 1));
        mx0 = fmaxf(mx0, __shfl_xor_sync(0xffffffffu, mx0, 2));
        mx1 = fmaxf(mx1, __shfl_xor_sync(0xffffffffu, mx1, 1));
        mx1 = fmaxf(mx1, __shfl_xor_sync(0xffffffffu, mx1, 2));

        const float mn0 = fmaxf(mrow[0], mx0);
        const float mn1 = fmaxf(mrow[1], mx1);
        const float al0 = ex2f(mrow[0] - mn0);
        const float al1 = ex2f(mrow[1] - mn1);
        mrow[0] = mn0; mrow[1] = mn1;

        float s0 = 0.f, s1 = 0.f;
#pragma unroll
        for (int nt = 0; nt < 8; nt++) {
            sc[nt][0] = ex2f(sc[nt][0] - mn0); s0 += sc[nt][0];
            sc[nt][1] = ex2f(sc[nt][1] - mn0); s0 += sc[nt][1];
            sc[nt][2] = ex2f(sc[nt][2] - mn1); s1 += sc[nt][2];
            sc[nt][3] = ex2f(sc[nt][3] - mn1); s1 += sc[nt][3];
        }
        s0 += __shfl_xor_sync(0xffffffffu, s0, 1);
        s0 += __shfl_xor_sync(0xffffffffu, s0, 2);
        s1 += __shfl_xor_sync(0xffffffffu, s1, 1);
        s1 += __shfl_xor_sync(0xffffffffu, s1, 2);
        lsum[0] = lsum[0] * al0 + s0;
        lsum[1] = lsum[1] * al1 + s1;

#pragma unroll
        for (int nt = 0; nt < 8; nt++) {
            so[nt][0] *= al0; so[nt][1] *= al0;
            so[nt][2] *= al1; so[nt][3] *= al1;
        }

        // ---- pack P to fp16 a-frags in registers (no smem round-trip) ----
        uint32_t pa[4][4];
#pragma unroll
        for (int kc = 0; kc < 4; kc++) {
            pa[kc][0] = pack_f16(sc[2 * kc][0],     sc[2 * kc][1]);
            pa[kc][1] = pack_f16(sc[2 * kc][2],     sc[2 * kc][3]);
            pa[kc][2] = pack_f16(sc[2 * kc + 1][0], sc[2 * kc + 1][1]);
            pa[kc][3] = pack_f16(sc[2 * kc + 1][2], sc[2 * kc + 1][3]);
        }

        // ---- O += P V : b-frags via ldmatrix.trans on [key][d] V tile ----
        // mat group at (key=kc*16, d=nt2*16): regs = (klo,dlo),(khi,dlo),(klo,dhi),(khi,dhi)
#pragma unroll
        for (int kc = 0; kc < 4; kc++) {
#pragma unroll
            for (int nt2 = 0; nt2 < 4; nt2++) {
                uint32_t bf[4];
                ldsm_x4_trans(bf, sV + (uint32_t)(((kc * 16) * AST + nt2 * 16) * 2) + vtoff);
                mma_f16(so[2 * nt2],     pa[kc], bf + 0);
                mma_f16(so[2 * nt2 + 1], pa[kc], bf + 2);
            }
        }
    }

    // ---- normalize + store y as fp16 (for fp16 GEMM2) ----
    {
        const float inv0 = 1.f / lsum[0];
        const float inv1 = 1.f / lsum[1];
        const int r0 = q0 + w * 16 + g;
        __half* yb = g_yh + (size_t)b * TLEN * CDIM + h * DH;
#pragma unroll
        for (int nt = 0; nt < 8; nt++) {
            const int c = nt * 8 + 2 * q;
            *(uint32_t*)(yb + (size_t)r0 * CDIM + c) =
                pack_f16(so[nt][0] * inv0, so[nt][1] * inv0);
            *(uint32_t*)(yb + (size_t)(r0 + 8) * CDIM + c) =
                pack_f16(so[nt][2] * inv1, so[nt][3] * inv1);
        }
    }
}

// ---------------------------------------------------------------------------
extern "C" void kernel_launch(void* const* d_in, const int* in_sizes, int n_in,
                              void* d_out, int out_size)
{
    const float* x      = (const float*)d_in[0];
    const float* W_attn = (const float*)d_in[1];
    const float* b_attn = (const float*)d_in[2];
    const float* W_proj = (const float*)d_in[3];
    const float* b_proj = (const float*)d_in[4];
    float* out = (float*)d_out;

    cudaFuncSetAttribute(gemm_h_kernel, cudaFuncAttributeMaxDynamicSharedMemorySize, HGSMEM);
    cudaFuncSetAttribute(attn_h_kernel, cudaFuncAttributeMaxDynamicSharedMemorySize, ASMEM);

    // 0) pre-convert x; transpose+convert weights (fp16, wide stores)
    cvt_kernel<<<(MROWS * CDIM) / (256 * 8), 256>>>(x);
    transpose_kernel<<<dim3((3 * CDIM) / 32, CDIM / 64), 256>>>(W_attn, CDIM, 3 * CDIM, 0);
    transpose_kernel<<<dim3(CDIM / 32, CDIM / 64), 256>>>(W_proj, CDIM, CDIM, 1);

    // 1) qkv = x @ W_attn + b_attn (fp16 in/out, fp32 accum)
    {
        dim3 grid((3 * CDIM) / 128, MROWS / 128);
        gemm_h_kernel<<<grid, 128, HGSMEM>>>(b_attn, nullptr, MROWS, 3 * CDIM, CDIM, 0);
    }
    // 2) flash attention (fp16 QK + fp16 PV, trans-V) -> g_yh
    {
        dim3 grid(TLEN / 64, HN, BSZ);
        attn_h_kernel<<<grid, 128, ASMEM>>>();
    }
    // 3) out = y @ W_proj + b_proj (fp16 in, fp32 accum + store)
    {
        dim3 grid(CDIM / 128, MROWS / 128);
        gemm_h_kernel<<<grid, 128, HGSMEM>>>(b_proj, out, MROWS, CDIM, CDIM, 1);
    }
}